// round 1
// baseline (speedup 1.0000x reference)
#include <cuda_runtime.h>
#include <math.h>

#define QLEN  512
#define MLEN  512
#define KLEN  1024
#define BSZ   8
#define NH    16
#define DH    64
#define DM    1024
#define HD    1024
#define DI    4096
#define NVOC  32000
#define NROWS (QLEN*BSZ)   /* 4096 */
#define KROWS (KLEN*BSZ)   /* 8192 */
#define ATT_SCALE 0.125f   /* 1/sqrt(64) */

/* ------------------------------------------------------------------ */
/* Static device scratch (allocation-free)                            */
/* ------------------------------------------------------------------ */
__device__ float g_core  [NROWS*DM];        /* 16.8 MB */
__device__ float g_xmem  [KROWS*DM];        /* 33.5 MB */
__device__ float g_q     [NROWS*HD];        /* 16.8 MB */
__device__ float g_kv    [KROWS*2*HD];      /* 67 MB   */
__device__ float g_rk    [KLEN*HD];         /* 4 MB    */
__device__ float g_posb  [KLEN*DM];         /* 4 MB    */
__device__ float g_score [67108864];        /* [bn=128][512][1024] 268 MB */
__device__ float g_vec   [NROWS*HD];        /* 16.8 MB */
__device__ float g_tmp   [NROWS*DM];        /* 16.8 MB */
__device__ float g_ff    [NROWS*DI];        /* 67 MB   */
__device__ float g_logits[131072000];       /* [4096][32000] 524 MB */

/* ------------------------------------------------------------------ */
/* Generic 128x128x8 SGEMM.  EPI: 0=none 1=+bias 2=+bias+relu         */
/* TB:  0 = B is [K,N] row-major (NN), 1 = B is [N,K] row-major (NT)  */
/* All M,N multiples of 128; K multiple of 8.                         */
/* ------------------------------------------------------------------ */
template<int EPI, int TB>
__global__ void __launch_bounds__(256) sgemm_kernel(
    const float* __restrict__ A, const float* __restrict__ B,
    const float* __restrict__ bias, float* __restrict__ C,
    int M, int N, int K)
{
    __shared__ float As[8][128];
    __shared__ float Bs[8][128];
    const int tid = threadIdx.x;
    const int bm = blockIdx.y * 128, bn = blockIdx.x * 128;
    const int arow = tid >> 1, acol = (tid & 1) * 4;   /* 128 rows x 8 cols */
    const int brow = tid >> 5, bcol = (tid & 31) * 4;  /* 8 rows x 128 cols */
    const int tx = tid & 15, ty = tid >> 4;

    float acc[8][8];
#pragma unroll
    for (int r = 0; r < 8; r++)
#pragma unroll
        for (int c = 0; c < 8; c++) acc[r][c] = 0.f;

    const float* Ap = A + (size_t)(bm + arow) * K + acol;

    for (int k0 = 0; k0 < K; k0 += 8) {
        float4 av = *(const float4*)(Ap + k0);
        As[acol+0][arow] = av.x; As[acol+1][arow] = av.y;
        As[acol+2][arow] = av.z; As[acol+3][arow] = av.w;
        if (TB == 0) {
            float4 bv = *(const float4*)(B + (size_t)(k0 + brow) * N + bn + bcol);
            *(float4*)&Bs[brow][bcol] = bv;
        } else {
            float4 bv = *(const float4*)(B + (size_t)(bn + arow) * K + k0 + acol);
            Bs[acol+0][arow] = bv.x; Bs[acol+1][arow] = bv.y;
            Bs[acol+2][arow] = bv.z; Bs[acol+3][arow] = bv.w;
        }
        __syncthreads();
#pragma unroll
        for (int kk = 0; kk < 8; kk++) {
            float ar[8], br[8];
            *(float4*)(ar)   = *(const float4*)&As[kk][ty*8];
            *(float4*)(ar+4) = *(const float4*)&As[kk][ty*8+4];
            *(float4*)(br)   = *(const float4*)&Bs[kk][tx*8];
            *(float4*)(br+4) = *(const float4*)&Bs[kk][tx*8+4];
#pragma unroll
            for (int r = 0; r < 8; r++)
#pragma unroll
                for (int c = 0; c < 8; c++) acc[r][c] += ar[r] * br[c];
        }
        __syncthreads();
    }
#pragma unroll
    for (int r = 0; r < 8; r++) {
        size_t m = (size_t)(bm + ty*8 + r);
#pragma unroll
        for (int c4 = 0; c4 < 8; c4 += 4) {
            int n = bn + tx*8 + c4;
            float4 v;
            v.x = acc[r][c4]; v.y = acc[r][c4+1]; v.z = acc[r][c4+2]; v.w = acc[r][c4+3];
            if (EPI >= 1) { v.x += bias[n]; v.y += bias[n+1]; v.z += bias[n+2]; v.w += bias[n+3]; }
            if (EPI == 2) { v.x = fmaxf(v.x,0.f); v.y = fmaxf(v.y,0.f); v.z = fmaxf(v.z,0.f); v.w = fmaxf(v.w,0.f); }
            *(float4*)(C + m * N + n) = v;
        }
    }
}

/* ------------------------------------------------------------------ */
/* Fused attention score kernel: score = (AC + BD_shifted)*SCALE      */
/* BD[i,j] = (q_i + rrb) . r_k[j + 511 - i]                            */
/* grid (jt=16, it=8, bn=128), 256 threads, 64x64 tile                 */
/* dynamic smem: 3*64*64 + 64*127 floats = 81664 bytes                 */
/* ------------------------------------------------------------------ */
__global__ void __launch_bounds__(256) score_kernel(
    const float* __restrict__ q, const float* __restrict__ kv,
    const float* __restrict__ rk,
    const float* __restrict__ rwb, const float* __restrict__ rrb,
    float* __restrict__ score)
{
    const int jt = blockIdx.x, it = blockIdx.y, bn = blockIdx.z;
    const int i0 = it * 64, j0 = jt * 64;
    if (j0 > i0 + 63 + MLEN) return;           /* fully masked tile */
    const int b = bn >> 4, n = bn & 15;

    extern __shared__ float sh[];
    float* sQW = sh;             /* [d][i] 64x64 */
    float* sQR = sh + 4096;      /* [d][i] */
    float* sK  = sh + 8192;      /* [d][j] */
    float* sRK = sh + 12288;     /* [d][lofs] 64x127 */

    const int tid = threadIdx.x;

    /* q tile with both biases */
    for (int s = tid; s < 1024; s += 256) {
        int row = s >> 4, d4 = (s & 15) << 2;
        float4 qv = *(const float4*)(q + ((size_t)(i0+row)*BSZ + b)*HD + n*DH + d4);
        float4 wv = *(const float4*)(rwb + n*DH + d4);
        float4 rv = *(const float4*)(rrb + n*DH + d4);
        sQW[(d4+0)*64+row] = qv.x + wv.x; sQW[(d4+1)*64+row] = qv.y + wv.y;
        sQW[(d4+2)*64+row] = qv.z + wv.z; sQW[(d4+3)*64+row] = qv.w + wv.w;
        sQR[(d4+0)*64+row] = qv.x + rv.x; sQR[(d4+1)*64+row] = qv.y + rv.y;
        sQR[(d4+2)*64+row] = qv.z + rv.z; sQR[(d4+3)*64+row] = qv.w + rv.w;
    }
    /* k tile */
    for (int s = tid; s < 1024; s += 256) {
        int row = s >> 4, d4 = (s & 15) << 2;
        float4 kvv = *(const float4*)(kv + ((size_t)(j0+row)*BSZ + b)*(2*HD) + n*DH + d4);
        sK[(d4+0)*64+row] = kvv.x; sK[(d4+1)*64+row] = kvv.y;
        sK[(d4+2)*64+row] = kvv.z; sK[(d4+3)*64+row] = kvv.w;
    }
    /* r_k window: rows lbase .. lbase+126  (lbase = j0 - i0 + 448 >= 0) */
    const int lbase = j0 - i0 + 448;
    for (int s = tid; s < 2032; s += 256) {
        int row = s >> 4, d4 = (s & 15) << 2;
        int l = lbase + row;
        float4 rv;
        if (l < KLEN) rv = *(const float4*)(rk + (size_t)l*HD + n*DH + d4);
        else          rv = make_float4(0.f,0.f,0.f,0.f);
        sRK[(d4+0)*127+row] = rv.x; sRK[(d4+1)*127+row] = rv.y;
        sRK[(d4+2)*127+row] = rv.z; sRK[(d4+3)*127+row] = rv.w;
    }
    __syncthreads();

    const int tx = tid & 15, ty = tid >> 4;
    const int ib = ty * 4, jb = tx * 4;
    const int base = jb - ib + 60;    /* lofs for (r,c) = base + 3 + c - r */
    float aA[4][4], aB[4][4];
#pragma unroll
    for (int r = 0; r < 4; r++)
#pragma unroll
        for (int c = 0; c < 4; c++) { aA[r][c] = 0.f; aB[r][c] = 0.f; }

    for (int d = 0; d < 64; d++) {
        float qw[4], qr2[4], kk[4], rw[7];
#pragma unroll
        for (int r = 0; r < 4; r++) { qw[r] = sQW[d*64+ib+r]; qr2[r] = sQR[d*64+ib+r]; }
#pragma unroll
        for (int c = 0; c < 4; c++) kk[c] = sK[d*64+jb+c];
#pragma unroll
        for (int e = 0; e < 7; e++) rw[e] = sRK[d*127+base+e];
#pragma unroll
        for (int r = 0; r < 4; r++)
#pragma unroll
            for (int c = 0; c < 4; c++) {
                aA[r][c] += qw[r] * kk[c];
                aB[r][c] += qr2[r] * rw[3 + c - r];
            }
    }
#pragma unroll
    for (int r = 0; r < 4; r++) {
        float4 v;
        v.x = (aA[r][0]+aB[r][0])*ATT_SCALE;
        v.y = (aA[r][1]+aB[r][1])*ATT_SCALE;
        v.z = (aA[r][2]+aB[r][2])*ATT_SCALE;
        v.w = (aA[r][3]+aB[r][3])*ATT_SCALE;
        *(float4*)(score + ((size_t)bn*QLEN + i0+ib+r)*KLEN + j0 + jb) = v;
    }
}

/* ------------------------------------------------------------------ */
/* Causal softmax over j (valid j <= i + 512); zero-fills the rest.   */
/* grid (i=512, bn=128), 256 threads                                   */
/* ------------------------------------------------------------------ */
__global__ void __launch_bounds__(256) softmax_kernel(float* __restrict__ score)
{
    const int i = blockIdx.x, bn = blockIdx.y;
    float* row = score + ((size_t)bn*QLEN + i)*KLEN;
    const int cnt = i + MLEN + 1;    /* valid entries */
    const int tid = threadIdx.x;
    __shared__ float red[256];

    float m = -1e30f;
    for (int j = tid; j < cnt; j += 256) m = fmaxf(m, row[j]);
    red[tid] = m; __syncthreads();
    for (int s = 128; s > 0; s >>= 1) { if (tid < s) red[tid] = fmaxf(red[tid], red[tid+s]); __syncthreads(); }
    m = red[0]; __syncthreads();

    float sum = 0.f;
    for (int j = tid; j < cnt; j += 256) sum += expf(row[j] - m);
    red[tid] = sum; __syncthreads();
    for (int s = 128; s > 0; s >>= 1) { if (tid < s) red[tid] += red[tid+s]; __syncthreads(); }
    const float inv = 1.f / red[0];

    for (int j = tid; j < cnt; j += 256) row[j] = expf(row[j] - m) * inv;
    for (int j = cnt + tid; j < KLEN; j += 256) row[j] = 0.f;
}

/* ------------------------------------------------------------------ */
/* vec[i,b,n,:] = prob[bn,i,:] @ v[:,b,n,:]   (skips masked j-chunks) */
/* grid (it=8, bn=128), 256 threads, 64(i) x 64(d), K-chunks of 64(j)  */
/* ------------------------------------------------------------------ */
__global__ void __launch_bounds__(256) pv_kernel(
    const float* __restrict__ prob, const float* __restrict__ kv,
    float* __restrict__ vec)
{
    const int it = blockIdx.x, bn = blockIdx.y;
    const int b = bn >> 4, n = bn & 15;
    const int i0 = it * 64;
    __shared__ float sP[64][65];   /* [j][i] */
    __shared__ float sV[64][64];   /* [j][d] */
    const int tid = threadIdx.x;
    const int tx = tid & 15, ty = tid >> 4;
    float acc[4][4];
#pragma unroll
    for (int r = 0; r < 4; r++)
#pragma unroll
        for (int c = 0; c < 4; c++) acc[r][c] = 0.f;

    const int jlimit = i0 + 63 + MLEN;
    for (int j0 = 0; j0 <= jlimit && j0 < KLEN; j0 += 64) {
        for (int s = tid; s < 1024; s += 256) {
            int row = s >> 4, c4 = (s & 15) << 2;
            float4 p = *(const float4*)(prob + ((size_t)bn*QLEN + i0 + row)*KLEN + j0 + c4);
            sP[c4+0][row] = p.x; sP[c4+1][row] = p.y; sP[c4+2][row] = p.z; sP[c4+3][row] = p.w;
            float4 vv = *(const float4*)(kv + ((size_t)(j0+row)*BSZ + b)*(2*HD) + HD + n*DH + c4);
            *(float4*)&sV[row][c4] = vv;
        }
        __syncthreads();
#pragma unroll 4
        for (int jj = 0; jj < 64; jj++) {
            float p4[4], v4[4];
#pragma unroll
            for (int r = 0; r < 4; r++) p4[r] = sP[jj][ty*4+r];
#pragma unroll
            for (int c = 0; c < 4; c++) v4[c] = sV[jj][tx*4+c];
#pragma unroll
            for (int r = 0; r < 4; r++)
#pragma unroll
                for (int c = 0; c < 4; c++) acc[r][c] += p4[r] * v4[c];
        }
        __syncthreads();
    }
#pragma unroll
    for (int r = 0; r < 4; r++) {
        float4 v; v.x = acc[r][0]; v.y = acc[r][1]; v.z = acc[r][2]; v.w = acc[r][3];
        *(float4*)(vec + ((size_t)(i0+ty*4+r)*BSZ + b)*HD + n*DH + tx*4) = v;
    }
}

/* ------------------------------------------------------------------ */
/* core = LayerNorm(core + delta) * g + b                              */
/* ------------------------------------------------------------------ */
__global__ void __launch_bounds__(256) add_ln_kernel(
    float* __restrict__ core, const float* __restrict__ delta,
    const float* __restrict__ gamma, const float* __restrict__ beta)
{
    const int row = blockIdx.x, tid = threadIdx.x;
    float* x = core + (size_t)row * DM;
    const float* d = delta + (size_t)row * DM;
    __shared__ float red[256];

    float v[4]; float s = 0.f;
#pragma unroll
    for (int e = 0; e < 4; e++) { int idx = tid + e*256; v[e] = x[idx] + d[idx]; s += v[e]; }
    red[tid] = s; __syncthreads();
    for (int st = 128; st > 0; st >>= 1) { if (tid < st) red[tid] += red[tid+st]; __syncthreads(); }
    const float mu = red[0] * (1.f / DM); __syncthreads();

    float sq = 0.f;
#pragma unroll
    for (int e = 0; e < 4; e++) { float t = v[e] - mu; sq += t * t; }
    red[tid] = sq; __syncthreads();
    for (int st = 128; st > 0; st >>= 1) { if (tid < st) red[tid] += red[tid+st]; __syncthreads(); }
    const float inv = rsqrtf(red[0] * (1.f / DM) + 1e-5f);
#pragma unroll
    for (int e = 0; e < 4; e++) {
        int idx = tid + e*256;
        x[idx] = (v[e] - mu) * inv * gamma[idx] + beta[idx];
    }
}

/* ------------------------------------------------------------------ */
/* Misc small kernels                                                  */
/* ------------------------------------------------------------------ */
__global__ void copy_kernel(float* __restrict__ dst, const float* __restrict__ src, int n4)
{
    int idx = blockIdx.x * blockDim.x + threadIdx.x;
    if (idx < n4) ((float4*)dst)[idx] = ((const float4*)src)[idx];
}

__global__ void embed_kernel(const int* __restrict__ data, const float* __restrict__ embW,
                             float* __restrict__ core)
{
    const int row = blockIdx.x;
    const int tok = data[row];
    ((float4*)(core + (size_t)row*DM))[threadIdx.x] =
        ((const float4*)(embW + (size_t)tok*DM))[threadIdx.x];
}

__global__ void pos_kernel(float* __restrict__ pos)
{
    const int l = blockIdx.x;
    const float fl = (float)(KLEN - 1 - l);
    for (int c = threadIdx.x; c < DM; c += 256) {
        int f = (c < 512) ? c : c - 512;
        float inv = expf(-((float)(2*f) / (float)DM) * 9.210340371976184f); /* ln(1e4) */
        float a = fl * inv;
        pos[(size_t)l*DM + c] = (c < 512) ? sinf(a) : cosf(a);
    }
}

__global__ void __launch_bounds__(256) loss_kernel(
    const float* __restrict__ logits, const int* __restrict__ target,
    float* __restrict__ out)
{
    const int row = blockIdx.x, tid = threadIdx.x;
    const float* L = logits + (size_t)row * NVOC;
    __shared__ float sm[256], ss[256];

    float m = -1e30f, s = 0.f;
    for (int v = tid; v < NVOC; v += 256) {
        float x = L[v];
        if (x > m) { s = s * expf(m - x) + 1.f; m = x; }
        else       { s += expf(x - m); }
    }
    sm[tid] = m; ss[tid] = s; __syncthreads();
    for (int st = 128; st > 0; st >>= 1) {
        if (tid < st) {
            float m2 = sm[tid+st], s2 = ss[tid+st];
            if (m2 > sm[tid]) { ss[tid] = ss[tid] * expf(sm[tid] - m2) + s2; sm[tid] = m2; }
            else              { ss[tid] += s2 * expf(m2 - sm[tid]); }
        }
        __syncthreads();
    }
    if (tid == 0) {
        float lse = sm[0] + logf(ss[0]);
        out[row] = lse - L[target[row]];
    }
}

/* ------------------------------------------------------------------ */
/* Host orchestration                                                  */
/* ------------------------------------------------------------------ */
#define SCORE_SMEM 81664

extern "C" void kernel_launch(void* const* d_in, const int* in_sizes, int n_in,
                              void* d_out, int out_size)
{
    (void)in_sizes; (void)n_in; (void)out_size;
    const int*   data   = (const int*)  d_in[0];
    const int*   target = (const int*)  d_in[1];
    const float* memory = (const float*)d_in[2];
    const float* embW   = (const float*)d_in[3];
    const float* rwb    = (const float*)d_in[4];
    const float* rrb    = (const float*)d_in[5];
    const float* Wq     = (const float*)d_in[6];
    const float* Wkv    = (const float*)d_in[7];
    const float* Wr     = (const float*)d_in[8];
    const float* Wo     = (const float*)d_in[9];
    const float* W1     = (const float*)d_in[10];
    const float* b1     = (const float*)d_in[11];
    const float* W2     = (const float*)d_in[12];
    const float* b2     = (const float*)d_in[13];
    const float* ln1g   = (const float*)d_in[14];
    const float* ln1b   = (const float*)d_in[15];
    const float* ln2g   = (const float*)d_in[16];
    const float* ln2b   = (const float*)d_in[17];
    float* out = (float*)d_out;

    float *core,*xmem,*qb,*kvb,*rkb,*posb,*score,*vecb,*tmpb,*ffb,*logits;
    cudaGetSymbolAddress((void**)&core,   g_core);
    cudaGetSymbolAddress((void**)&xmem,   g_xmem);
    cudaGetSymbolAddress((void**)&qb,     g_q);
    cudaGetSymbolAddress((void**)&kvb,    g_kv);
    cudaGetSymbolAddress((void**)&rkb,    g_rk);
    cudaGetSymbolAddress((void**)&posb,   g_posb);
    cudaGetSymbolAddress((void**)&score,  g_score);
    cudaGetSymbolAddress((void**)&vecb,   g_vec);
    cudaGetSymbolAddress((void**)&tmpb,   g_tmp);
    cudaGetSymbolAddress((void**)&ffb,    g_ff);
    cudaGetSymbolAddress((void**)&logits, g_logits);

    cudaFuncSetAttribute(score_kernel, cudaFuncAttributeMaxDynamicSharedMemorySize, SCORE_SMEM);

    embed_kernel<<<NROWS, 256>>>(data, embW, core);
    pos_kernel<<<KLEN, 256>>>(posb);

    const int CP4 = NROWS*DM/4;      /* 1048576 float4 per 4096x1024 buffer */

    for (int l = 0; l < 6; l++) {
        /* hids[l] -> new_mems[l] */
        copy_kernel<<<4096, 256>>>(out + 4096 + (size_t)l*NROWS*DM, core, CP4);
        /* xmem = [mem[l]; core] */
        copy_kernel<<<4096, 256>>>(xmem, memory + (size_t)l*MLEN*BSZ*DM, CP4);
        copy_kernel<<<4096, 256>>>(xmem + (size_t)MLEN*BSZ*DM, core, CP4);

        sgemm_kernel<0,0><<<dim3(HD/128,   NROWS/128), 256>>>(core, Wq  + (size_t)l*DM*HD,   nullptr, qb,  NROWS, HD,   DM);
        sgemm_kernel<0,0><<<dim3(2*HD/128, KROWS/128), 256>>>(xmem, Wkv + (size_t)l*DM*2*HD, nullptr, kvb, KROWS, 2*HD, DM);
        sgemm_kernel<0,0><<<dim3(HD/128,   KLEN/128),  256>>>(posb, Wr  + (size_t)l*DM*HD,   nullptr, rkb, KLEN,  HD,   DM);

        score_kernel<<<dim3(16, 8, 128), 256, SCORE_SMEM>>>(qb, kvb, rkb, rwb, rrb, score);
        softmax_kernel<<<dim3(QLEN, 128), 256>>>(score);
        pv_kernel<<<dim3(8, 128), 256>>>(score, kvb, vecb);

        sgemm_kernel<0,0><<<dim3(DM/128, NROWS/128), 256>>>(vecb, Wo + (size_t)l*HD*DM, nullptr, tmpb, NROWS, DM, HD);
        add_ln_kernel<<<NROWS, 256>>>(core, tmpb, ln1g + l*DM, ln1b + l*DM);

        sgemm_kernel<2,0><<<dim3(DI/128, NROWS/128), 256>>>(core, W1 + (size_t)l*DM*DI, b1 + l*DI, ffb,  NROWS, DI, DM);
        sgemm_kernel<1,0><<<dim3(DM/128, NROWS/128), 256>>>(ffb,  W2 + (size_t)l*DI*DM, b2 + l*DM, tmpb, NROWS, DM, DI);
        add_ln_kernel<<<NROWS, 256>>>(core, tmpb, ln2g + l*DM, ln2b + l*DM);
    }

    /* tied softmax head: logits = core @ embW^T, then loss */
    sgemm_kernel<0,1><<<dim3(NVOC/128, NROWS/128), 256>>>(core, embW, nullptr, logits, NROWS, NVOC, DM);
    loss_kernel<<<NROWS, 256>>>(logits, target, out);
}

// round 4
// speedup vs baseline: 1.0017x; 1.0017x over previous
#include <cuda_runtime.h>
#include <math.h>

#define QLEN  512
#define MLEN  512
#define KLEN  1024
#define BSZ   8
#define NH    16
#define DH    64
#define DM    1024
#define HD    1024
#define DI    4096
#define NVOC  32000
#define NROWS (QLEN*BSZ)   /* 4096 */
#define KROWS (KLEN*BSZ)   /* 8192 */
#define ATT_SCALE 0.125f   /* 1/sqrt(64) */

/* ------------------------------------------------------------------ */
/* Static device scratch (allocation-free)                            */
/* ------------------------------------------------------------------ */
__device__ float g_core  [NROWS*DM];        /* 16.8 MB */
__device__ float g_xmem  [KROWS*DM];        /* 33.5 MB */
__device__ float g_q     [NROWS*HD];        /* 16.8 MB */
__device__ float g_kv    [KROWS*2*HD];      /* 67 MB   */
__device__ float g_rk    [KLEN*HD];         /* 4 MB    */
__device__ float g_posb  [KLEN*DM];         /* 4 MB    */
__device__ float g_score [67108864];        /* [bn=128][512][1024] 268 MB */
__device__ float g_vec   [NROWS*HD];        /* 16.8 MB */
__device__ float g_tmp   [NROWS*DM];        /* 16.8 MB */
__device__ float g_ff    [NROWS*DI];        /* 67 MB   */
__device__ float g_logits[131072000];       /* [4096][32000] 524 MB */

/* ------------------------------------------------------------------ */
/* Generic 128x128x8 SGEMM.  EPI: 0=none 1=+bias 2=+bias+relu         */
/* TB:  0 = B is [K,N] row-major (NN), 1 = B is [N,K] row-major (NT)  */
/* All M,N multiples of 128; K multiple of 8.                         */
/* ------------------------------------------------------------------ */
template<int EPI, int TB>
__global__ void __launch_bounds__(256) sgemm_kernel(
    const float* __restrict__ A, const float* __restrict__ B,
    const float* __restrict__ bias, float* __restrict__ C,
    int M, int N, int K)
{
    __shared__ float As[8][128];
    __shared__ float Bs[8][128];
    const int tid = threadIdx.x;
    const int bm = blockIdx.y * 128, bn = blockIdx.x * 128;
    const int arow = tid >> 1, acol = (tid & 1) * 4;   /* 128 rows x 8 cols */
    const int brow = tid >> 5, bcol = (tid & 31) * 4;  /* 8 rows x 128 cols */
    const int tx = tid & 15, ty = tid >> 4;

    float acc[8][8];
#pragma unroll
    for (int r = 0; r < 8; r++)
#pragma unroll
        for (int c = 0; c < 8; c++) acc[r][c] = 0.f;

    const float* Ap = A + (size_t)(bm + arow) * K + acol;

    for (int k0 = 0; k0 < K; k0 += 8) {
        float4 av = *(const float4*)(Ap + k0);
        As[acol+0][arow] = av.x; As[acol+1][arow] = av.y;
        As[acol+2][arow] = av.z; As[acol+3][arow] = av.w;
        if (TB == 0) {
            float4 bv = *(const float4*)(B + (size_t)(k0 + brow) * N + bn + bcol);
            *(float4*)&Bs[brow][bcol] = bv;
        } else {
            float4 bv = *(const float4*)(B + (size_t)(bn + arow) * K + k0 + acol);
            Bs[acol+0][arow] = bv.x; Bs[acol+1][arow] = bv.y;
            Bs[acol+2][arow] = bv.z; Bs[acol+3][arow] = bv.w;
        }
        __syncthreads();
#pragma unroll
        for (int kk = 0; kk < 8; kk++) {
            float ar[8], br[8];
            *(float4*)(ar)   = *(const float4*)&As[kk][ty*8];
            *(float4*)(ar+4) = *(const float4*)&As[kk][ty*8+4];
            *(float4*)(br)   = *(const float4*)&Bs[kk][tx*8];
            *(float4*)(br+4) = *(const float4*)&Bs[kk][tx*8+4];
#pragma unroll
            for (int r = 0; r < 8; r++)
#pragma unroll
                for (int c = 0; c < 8; c++) acc[r][c] += ar[r] * br[c];
        }
        __syncthreads();
    }
#pragma unroll
    for (int r = 0; r < 8; r++) {
        size_t m = (size_t)(bm + ty*8 + r);
#pragma unroll
        for (int c4 = 0; c4 < 8; c4 += 4) {
            int n = bn + tx*8 + c4;
            float4 v;
            v.x = acc[r][c4]; v.y = acc[r][c4+1]; v.z = acc[r][c4+2]; v.w = acc[r][c4+3];
            if (EPI >= 1) { v.x += bias[n]; v.y += bias[n+1]; v.z += bias[n+2]; v.w += bias[n+3]; }
            if (EPI == 2) { v.x = fmaxf(v.x,0.f); v.y = fmaxf(v.y,0.f); v.z = fmaxf(v.z,0.f); v.w = fmaxf(v.w,0.f); }
            *(float4*)(C + m * N + n) = v;
        }
    }
}

/* ------------------------------------------------------------------ */
/* Fused attention score kernel: score = (AC + BD_shifted)*SCALE      */
/* BD[i,j] = (q_i + rrb) . r_k[j + 511 - i]                            */
/* grid (jt=16, it=8, bn=128), 256 threads, 64x64 tile                 */
/* dynamic smem: 3*64*64 + 64*127 floats = 81664 bytes                 */
/* ------------------------------------------------------------------ */
__global__ void __launch_bounds__(256) score_kernel(
    const float* __restrict__ q, const float* __restrict__ kv,
    const float* __restrict__ rk,
    const float* __restrict__ rwb, const float* __restrict__ rrb,
    float* __restrict__ score)
{
    const int jt = blockIdx.x, it = blockIdx.y, bn = blockIdx.z;
    const int i0 = it * 64, j0 = jt * 64;
    if (j0 > i0 + 63 + MLEN) return;           /* fully masked tile */
    const int b = bn >> 4, n = bn & 15;

    extern __shared__ float sh[];
    float* sQW = sh;             /* [d][i] 64x64 */
    float* sQR = sh + 4096;      /* [d][i] */
    float* sK  = sh + 8192;      /* [d][j] */
    float* sRK = sh + 12288;     /* [d][lofs] 64x127 */

    const int tid = threadIdx.x;

    /* q tile with both biases */
    for (int s = tid; s < 1024; s += 256) {
        int row = s >> 4, d4 = (s & 15) << 2;
        float4 qv = *(const float4*)(q + ((size_t)(i0+row)*BSZ + b)*HD + n*DH + d4);
        float4 wv = *(const float4*)(rwb + n*DH + d4);
        float4 rv = *(const float4*)(rrb + n*DH + d4);
        sQW[(d4+0)*64+row] = qv.x + wv.x; sQW[(d4+1)*64+row] = qv.y + wv.y;
        sQW[(d4+2)*64+row] = qv.z + wv.z; sQW[(d4+3)*64+row] = qv.w + wv.w;
        sQR[(d4+0)*64+row] = qv.x + rv.x; sQR[(d4+1)*64+row] = qv.y + rv.y;
        sQR[(d4+2)*64+row] = qv.z + rv.z; sQR[(d4+3)*64+row] = qv.w + rv.w;
    }
    /* k tile */
    for (int s = tid; s < 1024; s += 256) {
        int row = s >> 4, d4 = (s & 15) << 2;
        float4 kvv = *(const float4*)(kv + ((size_t)(j0+row)*BSZ + b)*(2*HD) + n*DH + d4);
        sK[(d4+0)*64+row] = kvv.x; sK[(d4+1)*64+row] = kvv.y;
        sK[(d4+2)*64+row] = kvv.z; sK[(d4+3)*64+row] = kvv.w;
    }
    /* r_k window: rows lbase .. lbase+126  (lbase = j0 - i0 + 448 >= 0) */
    const int lbase = j0 - i0 + 448;
    for (int s = tid; s < 2032; s += 256) {
        int row = s >> 4, d4 = (s & 15) << 2;
        int l = lbase + row;
        float4 rv;
        if (l < KLEN) rv = *(const float4*)(rk + (size_t)l*HD + n*DH + d4);
        else          rv = make_float4(0.f,0.f,0.f,0.f);
        sRK[(d4+0)*127+row] = rv.x; sRK[(d4+1)*127+row] = rv.y;
        sRK[(d4+2)*127+row] = rv.z; sRK[(d4+3)*127+row] = rv.w;
    }
    __syncthreads();

    const int tx = tid & 15, ty = tid >> 4;
    const int ib = ty * 4, jb = tx * 4;
    const int base = jb - ib + 60;    /* lofs for (r,c) = base + 3 + c - r */
    float aA[4][4], aB[4][4];
#pragma unroll
    for (int r = 0; r < 4; r++)
#pragma unroll
        for (int c = 0; c < 4; c++) { aA[r][c] = 0.f; aB[r][c] = 0.f; }

    for (int d = 0; d < 64; d++) {
        float qw[4], qr2[4], kk[4], rw[7];
#pragma unroll
        for (int r = 0; r < 4; r++) { qw[r] = sQW[d*64+ib+r]; qr2[r] = sQR[d*64+ib+r]; }
#pragma unroll
        for (int c = 0; c < 4; c++) kk[c] = sK[d*64+jb+c];
#pragma unroll
        for (int e = 0; e < 7; e++) rw[e] = sRK[d*127+base+e];
#pragma unroll
        for (int r = 0; r < 4; r++)
#pragma unroll
            for (int c = 0; c < 4; c++) {
                aA[r][c] += qw[r] * kk[c];
                aB[r][c] += qr2[r] * rw[3 + c - r];
            }
    }
#pragma unroll
    for (int r = 0; r < 4; r++) {
        float4 v;
        v.x = (aA[r][0]+aB[r][0])*ATT_SCALE;
        v.y = (aA[r][1]+aB[r][1])*ATT_SCALE;
        v.z = (aA[r][2]+aB[r][2])*ATT_SCALE;
        v.w = (aA[r][3]+aB[r][3])*ATT_SCALE;
        *(float4*)(score + ((size_t)bn*QLEN + i0+ib+r)*KLEN + j0 + jb) = v;
    }
}

/* ------------------------------------------------------------------ */
/* Causal softmax over j (valid j <= i + 512); zero-fills the rest.   */
/* grid (i=512, bn=128), 256 threads                                   */
/* ------------------------------------------------------------------ */
__global__ void __launch_bounds__(256) softmax_kernel(float* __restrict__ score)
{
    const int i = blockIdx.x, bn = blockIdx.y;
    float* row = score + ((size_t)bn*QLEN + i)*KLEN;
    const int cnt = i + MLEN + 1;    /* valid entries */
    const int tid = threadIdx.x;
    __shared__ float red[256];

    float m = -1e30f;
    for (int j = tid; j < cnt; j += 256) m = fmaxf(m, row[j]);
    red[tid] = m; __syncthreads();
    for (int s = 128; s > 0; s >>= 1) { if (tid < s) red[tid] = fmaxf(red[tid], red[tid+s]); __syncthreads(); }
    m = red[0]; __syncthreads();

    float sum = 0.f;
    for (int j = tid; j < cnt; j += 256) sum += expf(row[j] - m);
    red[tid] = sum; __syncthreads();
    for (int s = 128; s > 0; s >>= 1) { if (tid < s) red[tid] += red[tid+s]; __syncthreads(); }
    const float inv = 1.f / red[0];

    for (int j = tid; j < cnt; j += 256) row[j] = expf(row[j] - m) * inv;
    for (int j = cnt + tid; j < KLEN; j += 256) row[j] = 0.f;
}

/* ------------------------------------------------------------------ */
/* vec[i,b,n,:] = prob[bn,i,:] @ v[:,b,n,:]   (skips masked j-chunks) */
/* grid (it=8, bn=128), 256 threads, 64(i) x 64(d), K-chunks of 64(j)  */
/* ------------------------------------------------------------------ */
__global__ void __launch_bounds__(256) pv_kernel(
    const float* __restrict__ prob, const float* __restrict__ kv,
    float* __restrict__ vec)
{
    const int it = blockIdx.x, bn = blockIdx.y;
    const int b = bn >> 4, n = bn & 15;
    const int i0 = it * 64;
    __shared__ float sP[64][65];   /* [j][i] */
    __shared__ float sV[64][64];   /* [j][d] */
    const int tid = threadIdx.x;
    const int tx = tid & 15, ty = tid >> 4;
    float acc[4][4];
#pragma unroll
    for (int r = 0; r < 4; r++)
#pragma unroll
        for (int c = 0; c < 4; c++) acc[r][c] = 0.f;

    const int jlimit = i0 + 63 + MLEN;
    for (int j0 = 0; j0 <= jlimit && j0 < KLEN; j0 += 64) {
        for (int s = tid; s < 1024; s += 256) {
            int row = s >> 4, c4 = (s & 15) << 2;
            float4 p = *(const float4*)(prob + ((size_t)bn*QLEN + i0 + row)*KLEN + j0 + c4);
            sP[c4+0][row] = p.x; sP[c4+1][row] = p.y; sP[c4+2][row] = p.z; sP[c4+3][row] = p.w;
            float4 vv = *(const float4*)(kv + ((size_t)(j0+row)*BSZ + b)*(2*HD) + HD + n*DH + c4);
            *(float4*)&sV[row][c4] = vv;
        }
        __syncthreads();
#pragma unroll 4
        for (int jj = 0; jj < 64; jj++) {
            float p4[4], v4[4];
#pragma unroll
            for (int r = 0; r < 4; r++) p4[r] = sP[jj][ty*4+r];
#pragma unroll
            for (int c = 0; c < 4; c++) v4[c] = sV[jj][tx*4+c];
#pragma unroll
            for (int r = 0; r < 4; r++)
#pragma unroll
                for (int c = 0; c < 4; c++) acc[r][c] += p4[r] * v4[c];
        }
        __syncthreads();
    }
#pragma unroll
    for (int r = 0; r < 4; r++) {
        float4 v; v.x = acc[r][0]; v.y = acc[r][1]; v.z = acc[r][2]; v.w = acc[r][3];
        *(float4*)(vec + ((size_t)(i0+ty*4+r)*BSZ + b)*HD + n*DH + tx*4) = v;
    }
}

/* ------------------------------------------------------------------ */
/* core = LayerNorm(core + delta) * g + b                              */
/* ------------------------------------------------------------------ */
__global__ void __launch_bounds__(256) add_ln_kernel(
    float* __restrict__ core, const float* __restrict__ delta,
    const float* __restrict__ gamma, const float* __restrict__ beta)
{
    const int row = blockIdx.x, tid = threadIdx.x;
    float* x = core + (size_t)row * DM;
    const float* d = delta + (size_t)row * DM;
    __shared__ float red[256];

    float v[4]; float s = 0.f;
#pragma unroll
    for (int e = 0; e < 4; e++) { int idx = tid + e*256; v[e] = x[idx] + d[idx]; s += v[e]; }
    red[tid] = s; __syncthreads();
    for (int st = 128; st > 0; st >>= 1) { if (tid < st) red[tid] += red[tid+st]; __syncthreads(); }
    const float mu = red[0] * (1.f / DM); __syncthreads();

    float sq = 0.f;
#pragma unroll
    for (int e = 0; e < 4; e++) { float t = v[e] - mu; sq += t * t; }
    red[tid] = sq; __syncthreads();
    for (int st = 128; st > 0; st >>= 1) { if (tid < st) red[tid] += red[tid+st]; __syncthreads(); }
    const float inv = rsqrtf(red[0] * (1.f / DM) + 1e-5f);
#pragma unroll
    for (int e = 0; e < 4; e++) {
        int idx = tid + e*256;
        x[idx] = (v[e] - mu) * inv * gamma[idx] + beta[idx];
    }
}

/* ------------------------------------------------------------------ */
/* Misc small kernels                                                  */
/* ------------------------------------------------------------------ */
__global__ void copy_kernel(float* __restrict__ dst, const float* __restrict__ src, int n4)
{
    int idx = blockIdx.x * blockDim.x + threadIdx.x;
    if (idx < n4) ((float4*)dst)[idx] = ((const float4*)src)[idx];
}

__global__ void embed_kernel(const int* __restrict__ data, const float* __restrict__ embW,
                             float* __restrict__ core)
{
    const int row = blockIdx.x;
    const int tok = data[row];
    ((float4*)(core + (size_t)row*DM))[threadIdx.x] =
        ((const float4*)(embW + (size_t)tok*DM))[threadIdx.x];
}

__global__ void pos_kernel(float* __restrict__ pos)
{
    const int l = blockIdx.x;
    const float fl = (float)(KLEN - 1 - l);
    for (int c = threadIdx.x; c < DM; c += 256) {
        int f = (c < 512) ? c : c - 512;
        float inv = expf(-((float)(2*f) / (float)DM) * 9.210340371976184f); /* ln(1e4) */
        float a = fl * inv;
        pos[(size_t)l*DM + c] = (c < 512) ? sinf(a) : cosf(a);
    }
}

__global__ void __launch_bounds__(256) loss_kernel(
    const float* __restrict__ logits, const int* __restrict__ target,
    float* __restrict__ out)
{
    const int row = blockIdx.x, tid = threadIdx.x;
    const float* L = logits + (size_t)row * NVOC;
    __shared__ float sm[256], ss[256];

    float m = -1e30f, s = 0.f;
    for (int v = tid; v < NVOC; v += 256) {
        float x = L[v];
        if (x > m) { s = s * expf(m - x) + 1.f; m = x; }
        else       { s += expf(x - m); }
    }
    sm[tid] = m; ss[tid] = s; __syncthreads();
    for (int st = 128; st > 0; st >>= 1) {
        if (tid < st) {
            float m2 = sm[tid+st], s2 = ss[tid+st];
            if (m2 > sm[tid]) { ss[tid] = ss[tid] * expf(sm[tid] - m2) + s2; sm[tid] = m2; }
            else              { ss[tid] += s2 * expf(m2 - sm[tid]); }
        }
        __syncthreads();
    }
    if (tid == 0) {
        float lse = sm[0] + logf(ss[0]);
        out[row] = lse - L[target[row]];
    }
}

/* ------------------------------------------------------------------ */
/* Host orchestration                                                  */
/* ------------------------------------------------------------------ */
#define SCORE_SMEM 81664

extern "C" void kernel_launch(void* const* d_in, const int* in_sizes, int n_in,
                              void* d_out, int out_size)
{
    (void)in_sizes; (void)n_in; (void)out_size;
    const int*   data   = (const int*)  d_in[0];
    const int*   target = (const int*)  d_in[1];
    const float* memory = (const float*)d_in[2];
    const float* embW   = (const float*)d_in[3];
    const float* rwb    = (const float*)d_in[4];
    const float* rrb    = (const float*)d_in[5];
    const float* Wq     = (const float*)d_in[6];
    const float* Wkv    = (const float*)d_in[7];
    const float* Wr     = (const float*)d_in[8];
    const float* Wo     = (const float*)d_in[9];
    const float* W1     = (const float*)d_in[10];
    const float* b1     = (const float*)d_in[11];
    const float* W2     = (const float*)d_in[12];
    const float* b2     = (const float*)d_in[13];
    const float* ln1g   = (const float*)d_in[14];
    const float* ln1b   = (const float*)d_in[15];
    const float* ln2g   = (const float*)d_in[16];
    const float* ln2b   = (const float*)d_in[17];
    float* out = (float*)d_out;

    float *core,*xmem,*qb,*kvb,*rkb,*posb,*score,*vecb,*tmpb,*ffb,*logits;
    cudaGetSymbolAddress((void**)&core,   g_core);
    cudaGetSymbolAddress((void**)&xmem,   g_xmem);
    cudaGetSymbolAddress((void**)&qb,     g_q);
    cudaGetSymbolAddress((void**)&kvb,    g_kv);
    cudaGetSymbolAddress((void**)&rkb,    g_rk);
    cudaGetSymbolAddress((void**)&posb,   g_posb);
    cudaGetSymbolAddress((void**)&score,  g_score);
    cudaGetSymbolAddress((void**)&vecb,   g_vec);
    cudaGetSymbolAddress((void**)&tmpb,   g_tmp);
    cudaGetSymbolAddress((void**)&ffb,    g_ff);
    cudaGetSymbolAddress((void**)&logits, g_logits);

    cudaFuncSetAttribute(score_kernel, cudaFuncAttributeMaxDynamicSharedMemorySize, SCORE_SMEM);

    embed_kernel<<<NROWS, 256>>>(data, embW, core);
    pos_kernel<<<KLEN, 256>>>(posb);

    const int CP4 = NROWS*DM/4;      /* 1048576 float4 per 4096x1024 buffer */

    for (int l = 0; l < 6; l++) {
        /* hids[l] -> new_mems[l] */
        copy_kernel<<<4096, 256>>>(out + 4096 + (size_t)l*NROWS*DM, core, CP4);
        /* xmem = [mem[l]; core] */
        copy_kernel<<<4096, 256>>>(xmem, memory + (size_t)l*MLEN*BSZ*DM, CP4);
        copy_kernel<<<4096, 256>>>(xmem + (size_t)MLEN*BSZ*DM, core, CP4);

        sgemm_kernel<0,0><<<dim3(HD/128,   NROWS/128), 256>>>(core, Wq  + (size_t)l*DM*HD,   nullptr, qb,  NROWS, HD,   DM);
        sgemm_kernel<0,0><<<dim3(2*HD/128, KROWS/128), 256>>>(xmem, Wkv + (size_t)l*DM*2*HD, nullptr, kvb, KROWS, 2*HD, DM);
        sgemm_kernel<0,0><<<dim3(HD/128,   KLEN/128),  256>>>(posb, Wr  + (size_t)l*DM*HD,   nullptr, rkb, KLEN,  HD,   DM);

        score_kernel<<<dim3(16, 8, 128), 256, SCORE_SMEM>>>(qb, kvb, rkb, rwb, rrb, score);
        softmax_kernel<<<dim3(QLEN, 128), 256>>>(score);
        pv_kernel<<<dim3(8, 128), 256>>>(score, kvb, vecb);

        sgemm_kernel<0,0><<<dim3(DM/128, NROWS/128), 256>>>(vecb, Wo + (size_t)l*HD*DM, nullptr, tmpb, NROWS, DM, HD);
        add_ln_kernel<<<NROWS, 256>>>(core, tmpb, ln1g + l*DM, ln1b + l*DM);

        sgemm_kernel<2,0><<<dim3(DI/128, NROWS/128), 256>>>(core, W1 + (size_t)l*DM*DI, b1 + l*DI, ffb,  NROWS, DI, DM);
        sgemm_kernel<1,0><<<dim3(DM/128, NROWS/128), 256>>>(ffb,  W2 + (size_t)l*DI*DM, b2 + l*DM, tmpb, NROWS, DM, DI);
        add_ln_kernel<<<NROWS, 256>>>(core, tmpb, ln2g + l*DM, ln2b + l*DM);
    }

    /* tied softmax head: logits = core @ embW^T, then loss */
    sgemm_kernel<0,1><<<dim3(NVOC/128, NROWS/128), 256>>>(core, embW, nullptr, logits, NROWS, NVOC, DM);
    loss_kernel<<<NROWS, 256>>>(logits, target, out);
}

// round 6
// speedup vs baseline: 1.7879x; 1.7849x over previous
#include <cuda_runtime.h>
#include <cuda_bf16.h>
#include <math.h>
#include <stdint.h>

#define QLEN 512
#define MLEN 512
#define KLEN 1024
#define BSZ 8
#define DH 64
#define DM 1024
#define HD 1024
#define DI 4096
#define NVOC 32000
#define NROWS 4096
#define KROWS 8192
#define ATT_SCALE 0.125f

typedef __nv_bfloat16 bf16;

__device__ __forceinline__ uint32_t smem_u32(const void* p){
    uint32_t a; asm("{ .reg .u64 t; cvta.to.shared.u64 t, %1; cvt.u32.u64 %0, t; }":"=r"(a):"l"(p)); return a;
}
__device__ __forceinline__ void cpa16(uint32_t dst, const void* src){
    asm volatile("cp.async.cg.shared.global [%0], [%1], 16;"::"r"(dst),"l"(src));
}
#define CPA_COMMIT() asm volatile("cp.async.commit_group;":::"memory")
#define CPA_WAIT1()  asm volatile("cp.async.wait_group 1;":::"memory")

__device__ __forceinline__ void ldm_x4(uint32_t& r0,uint32_t& r1,uint32_t& r2,uint32_t& r3,uint32_t a){
    asm volatile("ldmatrix.sync.aligned.m8n8.x4.shared.b16 {%0,%1,%2,%3}, [%4];"
        :"=r"(r0),"=r"(r1),"=r"(r2),"=r"(r3):"r"(a));
}
__device__ __forceinline__ void ldm_x2(uint32_t& r0,uint32_t& r1,uint32_t a){
    asm volatile("ldmatrix.sync.aligned.m8n8.x2.shared.b16 {%0,%1}, [%2];"
        :"=r"(r0),"=r"(r1):"r"(a));
}
__device__ __forceinline__ void mma16816(float* c, const uint32_t* a, const uint32_t* b){
    asm volatile("mma.sync.aligned.m16n8k16.row.col.f32.bf16.bf16.f32 "
        "{%0,%1,%2,%3}, {%4,%5,%6,%7}, {%8,%9}, {%0,%1,%2,%3};"
        : "+f"(c[0]),"+f"(c[1]),"+f"(c[2]),"+f"(c[3])
        : "r"(a[0]),"r"(a[1]),"r"(a[2]),"r"(a[3]),"r"(b[0]),"r"(b[1]));
}

/* -------- static scratch -------- */
__device__ float g_core[NROWS*DM];
__device__ float g_q[NROWS*HD];
__device__ float g_kv[KROWS*2*HD];
__device__ float g_rk[KLEN*HD];
__device__ float g_posb[KLEN*DM];
__device__ float g_score[67108864];
__device__ float g_vec[NROWS*HD];
__device__ float g_tmp[NROWS*DM];
__device__ float g_ff[NROWS*DI];
__device__ float g_logits[131072000];
__device__ bf16 g_wqT_h[6*DM*HD],    g_wqT_l[6*DM*HD];
__device__ bf16 g_wkvT_h[6*DM*2*HD], g_wkvT_l[6*DM*2*HD];
__device__ bf16 g_wrT_h[6*DM*HD],    g_wrT_l[6*DM*HD];
__device__ bf16 g_woT_h[6*HD*DM],    g_woT_l[6*HD*DM];
__device__ bf16 g_w1T_h[6*DM*DI],    g_w1T_l[6*DM*DI];
__device__ bf16 g_w2T_h[6*DI*DM],    g_w2T_l[6*DI*DM];
__device__ bf16 g_embB_h[NVOC*DM],   g_embB_l[NVOC*DM];
__device__ bf16 g_cA_h[NROWS*DM], g_cA_l[NROWS*DM];
__device__ bf16 g_xA_h[KROWS*DM], g_xA_l[KROWS*DM];
__device__ bf16 g_vA_h[NROWS*HD], g_vA_l[NROWS*HD];
__device__ bf16 g_fA_h[NROWS*DI], g_fA_l[NROWS*DI];
__device__ bf16 g_pA_h[KLEN*DM],  g_pA_l[KLEN*DM];

/* -------- converters -------- */
__global__ void conv_hl_kernel(const float* __restrict__ in,
    bf16* __restrict__ h, bf16* __restrict__ l, int n4)
{
    int i = blockIdx.x*blockDim.x + threadIdx.x;
    if(i >= n4) return;
    float4 v = ((const float4*)in)[i];
    bf16 hx=__float2bfloat16(v.x), hy=__float2bfloat16(v.y);
    bf16 hz=__float2bfloat16(v.z), hw=__float2bfloat16(v.w);
    ((__nv_bfloat162*)h)[2*i]   = __halves2bfloat162(hx,hy);
    ((__nv_bfloat162*)h)[2*i+1] = __halves2bfloat162(hz,hw);
    ((__nv_bfloat162*)l)[2*i]   = __halves2bfloat162(__float2bfloat16(v.x-__bfloat162float(hx)),
                                                     __float2bfloat16(v.y-__bfloat162float(hy)));
    ((__nv_bfloat162*)l)[2*i+1] = __halves2bfloat162(__float2bfloat16(v.z-__bfloat162float(hz)),
                                                     __float2bfloat16(v.w-__bfloat162float(hw)));
}
/* [K,N] fp32 (layer z) -> [N,K] hi/lo bf16 */
__global__ void convT_kernel(const float* __restrict__ in,
    bf16* __restrict__ h, bf16* __restrict__ l, int K, int N)
{
    __shared__ float t[32][33];
    const int n0 = blockIdx.x*32, k0 = blockIdx.y*32;
    const size_t lay = (size_t)blockIdx.z*K*N;
    const int tx = threadIdx.x, ty = threadIdx.y;
#pragma unroll
    for(int e=0;e<4;e++) t[ty+8*e][tx] = in[lay + (size_t)(k0+ty+8*e)*N + n0+tx];
    __syncthreads();
#pragma unroll
    for(int e=0;e<4;e++){
        float x = t[tx][ty+8*e];
        size_t o = lay + (size_t)(n0+ty+8*e)*K + k0+tx;
        bf16 hx = __float2bfloat16(x);
        h[o] = hx; l[o] = __float2bfloat16(x-__bfloat162float(hx));
    }
}

/* -------- mma.sync split-bf16 GEMM: C[M,N] = A[M,K] @ B[N,K]^T --------
 * 128x128 tile, 8 warps (2M x 4N), warp tile 64x32, BK=32, 3-stage cp.async.
 * SMEM rows padded to 80B (stride 40 elems): conflict-free ldmatrix.
 */
#define MSTRIDE 40                 /* elements per smem row */
#define MASTG   (128*MSTRIDE)      /* elements per A (or B) stage */
#define MSTGE   (2*MASTG)          /* elements per full stage */
#define MSMEM   (3*MSTGE*2)        /* bytes: 61440 */

template<int EPI>
__global__ void __launch_bounds__(256,2) mgemm(
    const bf16* __restrict__ Ah, const bf16* __restrict__ Al,
    const bf16* __restrict__ Bh, const bf16* __restrict__ Bl,
    const float* __restrict__ bias, float* __restrict__ C, int M, int N, int K)
{
    extern __shared__ bf16 sm[];
    const uint32_t sb = smem_u32(sm);
    const int tid = threadIdx.x, lane = tid & 31, wid = tid >> 5;
    const int warpM = wid >> 2, warpN = wid & 3;
    const int m0 = blockIdx.x*128, n0 = blockIdx.y*128;
    const int NCK = K >> 5, TOT = 3*NCK;

    float acc[4][4][4];
#pragma unroll
    for(int mi=0;mi<4;mi++)
#pragma unroll
        for(int ni=0;ni<4;ni++)
#pragma unroll
            for(int e=0;e<4;e++) acc[mi][ni][e] = 0.f;

    const int lr0 = tid >> 2,        lk0 = tid & 3;          /* unit (r,ku) for g=0 */
    const int lr1 = (tid+256) >> 2,  lk1 = (tid+256) & 3;    /* g=1 */

    auto load_chunk = [&](int c, int buf){
        int pass = c / NCK, kc = c - pass*NCK, k0 = kc << 5;
        const bf16* A = (pass==2) ? Al : Ah;
        const bf16* B = (pass==1) ? Bl : Bh;
        uint32_t ab = sb + buf*(MSTGE*2);
        uint32_t bb = ab + MASTG*2;
        cpa16(ab + lr0*80 + lk0*16, A + (size_t)(m0+lr0)*K + k0 + lk0*8);
        cpa16(ab + lr1*80 + lk1*16, A + (size_t)(m0+lr1)*K + k0 + lk1*8);
        cpa16(bb + lr0*80 + lk0*16, B + (size_t)(n0+lr0)*K + k0 + lk0*8);
        cpa16(bb + lr1*80 + lk1*16, B + (size_t)(n0+lr1)*K + k0 + lk1*8);
    };

    load_chunk(0,0); CPA_COMMIT();
    load_chunk(1,1); CPA_COMMIT();

    const int arow = warpM*64 + (lane & 15);
    const int ahalf = lane >> 4;
    const int brow = warpN*32 + (lane & 7);
    const int bhalf = (lane >> 3) & 1;

    for(int c = 0; c < TOT; c++){
        CPA_WAIT1();
        __syncthreads();
        if(c+2 < TOT) load_chunk(c+2, (c+2)%3);
        CPA_COMMIT();

        const int buf = c % 3;
        uint32_t ab = sb + buf*(MSTGE*2);
        uint32_t bb = ab + MASTG*2;
#pragma unroll
        for(int ks=0; ks<2; ks++){
            uint32_t af[4][4], bf[4][2];
#pragma unroll
            for(int mi=0;mi<4;mi++)
                ldm_x4(af[mi][0],af[mi][1],af[mi][2],af[mi][3],
                       ab + (arow + mi*16)*80 + (ks*2 + ahalf)*16);
#pragma unroll
            for(int ni=0;ni<4;ni++)
                ldm_x2(bf[ni][0],bf[ni][1],
                       bb + (brow + ni*8)*80 + (ks*2 + bhalf)*16);
#pragma unroll
            for(int mi=0;mi<4;mi++)
#pragma unroll
                for(int ni=0;ni<4;ni++)
                    mma16816(acc[mi][ni], af[mi], bf[ni]);
        }
    }

    /* epilogue: direct stores (8B pairs; 32B-sector aligned per quad) */
#pragma unroll
    for(int mi=0;mi<4;mi++){
        const int row = m0 + warpM*64 + mi*16 + (lane>>2);
#pragma unroll
        for(int ni=0;ni<4;ni++){
            const int col = n0 + warpN*32 + ni*8 + (lane&3)*2;
            float c0=acc[mi][ni][0], c1=acc[mi][ni][1];
            float c2=acc[mi][ni][2], c3=acc[mi][ni][3];
            if(EPI>=1){
                float b0 = bias[col], b1 = bias[col+1];
                c0+=b0; c1+=b1; c2+=b0; c3+=b1;
            }
            if(EPI==2){
                c0=fmaxf(c0,0.f); c1=fmaxf(c1,0.f);
                c2=fmaxf(c2,0.f); c3=fmaxf(c3,0.f);
            }
            *(float2*)(C + (size_t)row*N + col)     = make_float2(c0,c1);
            *(float2*)(C + (size_t)(row+8)*N + col) = make_float2(c2,c3);
        }
    }
}

/* -------- attention (fp32) -------- */
__global__ void __launch_bounds__(256) score_kernel(
    const float* __restrict__ q, const float* __restrict__ kv, const float* __restrict__ rk,
    const float* __restrict__ rwb, const float* __restrict__ rrb, float* __restrict__ score)
{
    const int jt=blockIdx.x, it=blockIdx.y, bn=blockIdx.z;
    const int i0=it*64, j0=jt*64;
    if(j0 > i0+63+MLEN) return;
    const int b=bn>>4, n=bn&15;
    extern __shared__ float sh[];
    float* sQW=sh; float* sQR=sh+4096; float* sK=sh+8192; float* sRK=sh+12288;
    const int tid=threadIdx.x;
    for(int s=tid;s<1024;s+=256){
        int row=s>>4, d4=(s&15)<<2;
        float4 qv=*(const float4*)(q+((size_t)(i0+row)*BSZ+b)*HD+n*DH+d4);
        float4 wv=*(const float4*)(rwb+n*DH+d4);
        float4 rv=*(const float4*)(rrb+n*DH+d4);
        sQW[(d4+0)*64+row]=qv.x+wv.x; sQW[(d4+1)*64+row]=qv.y+wv.y;
        sQW[(d4+2)*64+row]=qv.z+wv.z; sQW[(d4+3)*64+row]=qv.w+wv.w;
        sQR[(d4+0)*64+row]=qv.x+rv.x; sQR[(d4+1)*64+row]=qv.y+rv.y;
        sQR[(d4+2)*64+row]=qv.z+rv.z; sQR[(d4+3)*64+row]=qv.w+rv.w;
    }
    for(int s=tid;s<1024;s+=256){
        int row=s>>4, d4=(s&15)<<2;
        float4 kvv=*(const float4*)(kv+((size_t)(j0+row)*BSZ+b)*(2*HD)+n*DH+d4);
        sK[(d4+0)*64+row]=kvv.x; sK[(d4+1)*64+row]=kvv.y;
        sK[(d4+2)*64+row]=kvv.z; sK[(d4+3)*64+row]=kvv.w;
    }
    const int lbase=j0-i0+448;
    for(int s=tid;s<2032;s+=256){
        int row=s>>4, d4=(s&15)<<2;
        int l=lbase+row;
        float4 rv;
        if(l<KLEN) rv=*(const float4*)(rk+(size_t)l*HD+n*DH+d4);
        else rv=make_float4(0.f,0.f,0.f,0.f);
        sRK[(d4+0)*127+row]=rv.x; sRK[(d4+1)*127+row]=rv.y;
        sRK[(d4+2)*127+row]=rv.z; sRK[(d4+3)*127+row]=rv.w;
    }
    __syncthreads();
    const int tx=tid&15, ty=tid>>4;
    const int ib=ty*4, jb=tx*4;
    const int base=jb-ib+60;
    float aA[4][4], aB[4][4];
#pragma unroll
    for(int r=0;r<4;r++)
#pragma unroll
        for(int c=0;c<4;c++){ aA[r][c]=0.f; aB[r][c]=0.f; }
    for(int d=0;d<64;d++){
        float qw[4],qr2[4],kk[4],rw[7];
#pragma unroll
        for(int r=0;r<4;r++){ qw[r]=sQW[d*64+ib+r]; qr2[r]=sQR[d*64+ib+r]; }
#pragma unroll
        for(int c=0;c<4;c++) kk[c]=sK[d*64+jb+c];
#pragma unroll
        for(int e=0;e<7;e++) rw[e]=sRK[d*127+base+e];
#pragma unroll
        for(int r=0;r<4;r++)
#pragma unroll
            for(int c=0;c<4;c++){ aA[r][c]+=qw[r]*kk[c]; aB[r][c]+=qr2[r]*rw[3+c-r]; }
    }
#pragma unroll
    for(int r=0;r<4;r++){
        float4 v;
        v.x=(aA[r][0]+aB[r][0])*ATT_SCALE; v.y=(aA[r][1]+aB[r][1])*ATT_SCALE;
        v.z=(aA[r][2]+aB[r][2])*ATT_SCALE; v.w=(aA[r][3]+aB[r][3])*ATT_SCALE;
        *(float4*)(score+((size_t)bn*QLEN+i0+ib+r)*KLEN+j0+jb)=v;
    }
}

__global__ void __launch_bounds__(256) softmax_kernel(float* __restrict__ score)
{
    const int i=blockIdx.x, bn=blockIdx.y;
    float* row = score + ((size_t)bn*QLEN+i)*KLEN;
    const int cnt = i+MLEN+1;
    const int tid = threadIdx.x;
    __shared__ float red[256];
    float m=-1e30f;
    for(int j=tid;j<cnt;j+=256) m=fmaxf(m,row[j]);
    red[tid]=m; __syncthreads();
    for(int s=128;s>0;s>>=1){ if(tid<s) red[tid]=fmaxf(red[tid],red[tid+s]); __syncthreads(); }
    m=red[0]; __syncthreads();
    float sum=0.f;
    for(int j=tid;j<cnt;j+=256) sum+=expf(row[j]-m);
    red[tid]=sum; __syncthreads();
    for(int s=128;s>0;s>>=1){ if(tid<s) red[tid]+=red[tid+s]; __syncthreads(); }
    const float inv=1.f/red[0];
    for(int j=tid;j<cnt;j+=256) row[j]=expf(row[j]-m)*inv;
    for(int j=cnt+tid;j<KLEN;j+=256) row[j]=0.f;
}

__global__ void __launch_bounds__(256) pv_kernel(
    const float* __restrict__ prob, const float* __restrict__ kv, float* __restrict__ vec)
{
    const int it=blockIdx.x, bn=blockIdx.y;
    const int b=bn>>4, n=bn&15;
    const int i0=it*64;
    __shared__ float sP[64][65];
    __shared__ float sV[64][64];
    const int tid=threadIdx.x;
    const int tx=tid&15, ty=tid>>4;
    float acc[4][4];
#pragma unroll
    for(int r=0;r<4;r++)
#pragma unroll
        for(int c=0;c<4;c++) acc[r][c]=0.f;
    const int jlimit=i0+63+MLEN;
    for(int j0=0;j0<=jlimit&&j0<KLEN;j0+=64){
        for(int s=tid;s<1024;s+=256){
            int row=s>>4, c4=(s&15)<<2;
            float4 p=*(const float4*)(prob+((size_t)bn*QLEN+i0+row)*KLEN+j0+c4);
            sP[c4+0][row]=p.x; sP[c4+1][row]=p.y; sP[c4+2][row]=p.z; sP[c4+3][row]=p.w;
            float4 vv=*(const float4*)(kv+((size_t)(j0+row)*BSZ+b)*(2*HD)+HD+n*DH+c4);
            *(float4*)&sV[row][c4]=vv;
        }
        __syncthreads();
#pragma unroll 4
        for(int jj=0;jj<64;jj++){
            float p4[4],v4[4];
#pragma unroll
            for(int r=0;r<4;r++) p4[r]=sP[jj][ty*4+r];
#pragma unroll
            for(int c=0;c<4;c++) v4[c]=sV[jj][tx*4+c];
#pragma unroll
            for(int r=0;r<4;r++)
#pragma unroll
                for(int c=0;c<4;c++) acc[r][c]+=p4[r]*v4[c];
        }
        __syncthreads();
    }
#pragma unroll
    for(int r=0;r<4;r++){
        float4 v; v.x=acc[r][0]; v.y=acc[r][1]; v.z=acc[r][2]; v.w=acc[r][3];
        *(float4*)(vec+((size_t)(i0+ty*4+r)*BSZ+b)*HD+n*DH+tx*4)=v;
    }
}

__global__ void __launch_bounds__(256) add_ln_kernel(
    float* __restrict__ core, const float* __restrict__ delta,
    const float* __restrict__ gamma, const float* __restrict__ beta)
{
    const int row=blockIdx.x, tid=threadIdx.x;
    float* x = core + (size_t)row*DM;
    const float* d = delta + (size_t)row*DM;
    __shared__ float red[256];
    float v[4]; float s=0.f;
#pragma unroll
    for(int e=0;e<4;e++){ int idx=tid+e*256; v[e]=x[idx]+d[idx]; s+=v[e]; }
    red[tid]=s; __syncthreads();
    for(int st=128;st>0;st>>=1){ if(tid<st) red[tid]+=red[tid+st]; __syncthreads(); }
    const float mu=red[0]*(1.f/DM); __syncthreads();
    float sq=0.f;
#pragma unroll
    for(int e=0;e<4;e++){ float t=v[e]-mu; sq+=t*t; }
    red[tid]=sq; __syncthreads();
    for(int st=128;st>0;st>>=1){ if(tid<st) red[tid]+=red[tid+st]; __syncthreads(); }
    const float inv=rsqrtf(red[0]*(1.f/DM)+1e-5f);
#pragma unroll
    for(int e=0;e<4;e++){ int idx=tid+e*256; x[idx]=(v[e]-mu)*inv*gamma[idx]+beta[idx]; }
}

__global__ void copy_kernel(float* __restrict__ dst, const float* __restrict__ src, int n4)
{
    int idx = blockIdx.x*blockDim.x + threadIdx.x;
    if(idx<n4) ((float4*)dst)[idx] = ((const float4*)src)[idx];
}
__global__ void embed_kernel(const int* __restrict__ data, const float* __restrict__ embW,
                             float* __restrict__ core)
{
    const int row = blockIdx.x;
    const int tok = data[row];
    ((float4*)(core+(size_t)row*DM))[threadIdx.x] = ((const float4*)(embW+(size_t)tok*DM))[threadIdx.x];
}
__global__ void pos_kernel(float* __restrict__ pos)
{
    const int l = blockIdx.x;
    const float fl = (float)(KLEN-1-l);
    for(int c=threadIdx.x;c<DM;c+=256){
        int f = (c<512)?c:c-512;
        float inv = expf(-((float)(2*f)/(float)DM)*9.210340371976184f);
        float a = fl*inv;
        pos[(size_t)l*DM+c] = (c<512)?sinf(a):cosf(a);
    }
}
__global__ void __launch_bounds__(256) loss_kernel(
    const float* __restrict__ logits, const int* __restrict__ target, float* __restrict__ out)
{
    const int row=blockIdx.x, tid=threadIdx.x;
    const float* L = logits + (size_t)row*NVOC;
    __shared__ float sm2[256], ss[256];
    float m=-1e30f, s=0.f;
    for(int v=tid;v<NVOC;v+=256){
        float x=L[v];
        if(x>m){ s=s*expf(m-x)+1.f; m=x; } else s+=expf(x-m);
    }
    sm2[tid]=m; ss[tid]=s; __syncthreads();
    for(int st=128;st>0;st>>=1){
        if(tid<st){
            float m2=sm2[tid+st], s2=ss[tid+st];
            if(m2>sm2[tid]){ ss[tid]=ss[tid]*expf(sm2[tid]-m2)+s2; sm2[tid]=m2; }
            else ss[tid]+=s2*expf(m2-sm2[tid]);
        }
        __syncthreads();
    }
    if(tid==0){ out[row] = sm2[0]+logf(ss[0]) - L[target[row]]; }
}

/* -------- host -------- */
#define SCORE_SMEM 81664

extern "C" void kernel_launch(void* const* d_in, const int* in_sizes, int n_in,
                              void* d_out, int out_size)
{
    (void)in_sizes; (void)n_in; (void)out_size;
    const int*   data   = (const int*)  d_in[0];
    const int*   target = (const int*)  d_in[1];
    const float* memory = (const float*)d_in[2];
    const float* embW   = (const float*)d_in[3];
    const float* rwb    = (const float*)d_in[4];
    const float* rrb    = (const float*)d_in[5];
    const float* Wq     = (const float*)d_in[6];
    const float* Wkv    = (const float*)d_in[7];
    const float* Wr     = (const float*)d_in[8];
    const float* Wo     = (const float*)d_in[9];
    const float* W1     = (const float*)d_in[10];
    const float* b1     = (const float*)d_in[11];
    const float* W2     = (const float*)d_in[12];
    const float* b2     = (const float*)d_in[13];
    const float* ln1g   = (const float*)d_in[14];
    const float* ln1b   = (const float*)d_in[15];
    const float* ln2g   = (const float*)d_in[16];
    const float* ln2b   = (const float*)d_in[17];
    float* out = (float*)d_out;

    float *core,*qb,*kvb,*rkb,*posb,*score,*vecb,*tmpb,*ffb,*logits;
    cudaGetSymbolAddress((void**)&core,g_core);   cudaGetSymbolAddress((void**)&qb,g_q);
    cudaGetSymbolAddress((void**)&kvb,g_kv);      cudaGetSymbolAddress((void**)&rkb,g_rk);
    cudaGetSymbolAddress((void**)&posb,g_posb);   cudaGetSymbolAddress((void**)&score,g_score);
    cudaGetSymbolAddress((void**)&vecb,g_vec);    cudaGetSymbolAddress((void**)&tmpb,g_tmp);
    cudaGetSymbolAddress((void**)&ffb,g_ff);      cudaGetSymbolAddress((void**)&logits,g_logits);

    bf16 *wqTh,*wqTl,*wkvTh,*wkvTl,*wrTh,*wrTl,*woTh,*woTl,*w1Th,*w1Tl,*w2Th,*w2Tl,*embBh,*embBl;
    bf16 *cAh,*cAl,*xAh,*xAl,*vAh,*vAl,*fAh,*fAl,*pAh,*pAl;
    cudaGetSymbolAddress((void**)&wqTh,g_wqT_h);   cudaGetSymbolAddress((void**)&wqTl,g_wqT_l);
    cudaGetSymbolAddress((void**)&wkvTh,g_wkvT_h); cudaGetSymbolAddress((void**)&wkvTl,g_wkvT_l);
    cudaGetSymbolAddress((void**)&wrTh,g_wrT_h);   cudaGetSymbolAddress((void**)&wrTl,g_wrT_l);
    cudaGetSymbolAddress((void**)&woTh,g_woT_h);   cudaGetSymbolAddress((void**)&woTl,g_woT_l);
    cudaGetSymbolAddress((void**)&w1Th,g_w1T_h);   cudaGetSymbolAddress((void**)&w1Tl,g_w1T_l);
    cudaGetSymbolAddress((void**)&w2Th,g_w2T_h);   cudaGetSymbolAddress((void**)&w2Tl,g_w2T_l);
    cudaGetSymbolAddress((void**)&embBh,g_embB_h); cudaGetSymbolAddress((void**)&embBl,g_embB_l);
    cudaGetSymbolAddress((void**)&cAh,g_cA_h); cudaGetSymbolAddress((void**)&cAl,g_cA_l);
    cudaGetSymbolAddress((void**)&xAh,g_xA_h); cudaGetSymbolAddress((void**)&xAl,g_xA_l);
    cudaGetSymbolAddress((void**)&vAh,g_vA_h); cudaGetSymbolAddress((void**)&vAl,g_vA_l);
    cudaGetSymbolAddress((void**)&fAh,g_fA_h); cudaGetSymbolAddress((void**)&fAl,g_fA_l);
    cudaGetSymbolAddress((void**)&pAh,g_pA_h); cudaGetSymbolAddress((void**)&pAl,g_pA_l);

    cudaFuncSetAttribute(score_kernel, cudaFuncAttributeMaxDynamicSharedMemorySize, SCORE_SMEM);
    cudaFuncSetAttribute(mgemm<0>, cudaFuncAttributeMaxDynamicSharedMemorySize, MSMEM);
    cudaFuncSetAttribute(mgemm<1>, cudaFuncAttributeMaxDynamicSharedMemorySize, MSMEM);
    cudaFuncSetAttribute(mgemm<2>, cudaFuncAttributeMaxDynamicSharedMemorySize, MSMEM);

    const dim3 cvt(32,8);
    convT_kernel<<<dim3(HD/32,DM/32,6),cvt>>>(Wq, wqTh, wqTl, DM, HD);
    convT_kernel<<<dim3(2*HD/32,DM/32,6),cvt>>>(Wkv, wkvTh, wkvTl, DM, 2*HD);
    convT_kernel<<<dim3(HD/32,DM/32,6),cvt>>>(Wr, wrTh, wrTl, DM, HD);
    convT_kernel<<<dim3(DM/32,HD/32,6),cvt>>>(Wo, woTh, woTl, HD, DM);
    convT_kernel<<<dim3(DI/32,DM/32,6),cvt>>>(W1, w1Th, w1Tl, DM, DI);
    convT_kernel<<<dim3(DM/32,DI/32,6),cvt>>>(W2, w2Th, w2Tl, DI, DM);
    conv_hl_kernel<<<NVOC*DM/4/256,256>>>(embW, embBh, embBl, NVOC*DM/4);

    embed_kernel<<<NROWS,256>>>(data, embW, core);
    pos_kernel<<<KLEN,256>>>(posb);
    conv_hl_kernel<<<KLEN*DM/4/256,256>>>(posb, pAh, pAl, KLEN*DM/4);

    const int CP4 = NROWS*DM/4;

    for(int l=0;l<6;l++){
        copy_kernel<<<4096,256>>>(out + 4096 + (size_t)l*NROWS*DM, core, CP4);

        conv_hl_kernel<<<CP4/256,256>>>(core, cAh, cAl, CP4);
        conv_hl_kernel<<<CP4/256,256>>>(memory + (size_t)l*MLEN*BSZ*DM, xAh, xAl, CP4);
        conv_hl_kernel<<<CP4/256,256>>>(core, xAh + (size_t)MLEN*BSZ*DM, xAl + (size_t)MLEN*BSZ*DM, CP4);

        mgemm<0><<<dim3(NROWS/128, HD/128),   256, MSMEM>>>(cAh, cAl, wqTh + (size_t)l*DM*HD,    wqTl + (size_t)l*DM*HD,    nullptr, qb,  NROWS, HD,   DM);
        mgemm<0><<<dim3(KROWS/128, 2*HD/128), 256, MSMEM>>>(xAh, xAl, wkvTh + (size_t)l*DM*2*HD, wkvTl + (size_t)l*DM*2*HD, nullptr, kvb, KROWS, 2*HD, DM);
        mgemm<0><<<dim3(KLEN/128, HD/128),    256, MSMEM>>>(pAh, pAl, wrTh + (size_t)l*DM*HD,    wrTl + (size_t)l*DM*HD,    nullptr, rkb, KLEN,  HD,   DM);

        score_kernel<<<dim3(16,8,128),256,SCORE_SMEM>>>(qb, kvb, rkb, rwb, rrb, score);
        softmax_kernel<<<dim3(QLEN,128),256>>>(score);
        pv_kernel<<<dim3(8,128),256>>>(score, kvb, vecb);

        conv_hl_kernel<<<CP4/256,256>>>(vecb, vAh, vAl, CP4);
        mgemm<0><<<dim3(NROWS/128, DM/128), 256, MSMEM>>>(vAh, vAl, woTh + (size_t)l*HD*DM, woTl + (size_t)l*HD*DM, nullptr, tmpb, NROWS, DM, HD);
        add_ln_kernel<<<NROWS,256>>>(core, tmpb, ln1g + l*DM, ln1b + l*DM);

        conv_hl_kernel<<<CP4/256,256>>>(core, cAh, cAl, CP4);
        mgemm<2><<<dim3(NROWS/128, DI/128), 256, MSMEM>>>(cAh, cAl, w1Th + (size_t)l*DM*DI, w1Tl + (size_t)l*DM*DI, b1 + l*DI, ffb, NROWS, DI, DM);
        conv_hl_kernel<<<NROWS*DI/4/256,256>>>(ffb, fAh, fAl, NROWS*DI/4);
        mgemm<1><<<dim3(NROWS/128, DM/128), 256, MSMEM>>>(fAh, fAl, w2Th + (size_t)l*DI*DM, w2Tl + (size_t)l*DI*DM, b2 + l*DM, tmpb, NROWS, DM, DI);
        add_ln_kernel<<<NROWS,256>>>(core, tmpb, ln2g + l*DM, ln2b + l*DM);
    }

    conv_hl_kernel<<<CP4/256,256>>>(core, cAh, cAl, CP4);
    mgemm<0><<<dim3(NROWS/128, NVOC/128), 256, MSMEM>>>(cAh, cAl, embBh, embBl, nullptr, logits, NROWS, NVOC, DM);
    loss_kernel<<<NROWS,256>>>(logits, target, out);
}

// round 10
// speedup vs baseline: 2.4049x; 1.3451x over previous
#include <cuda_runtime.h>
#include <cuda_bf16.h>
#include <math.h>
#include <stdint.h>

#define QLEN 512
#define MLEN 512
#define KLEN 1024
#define BSZ 8
#define DH 64
#define DM 1024
#define HD 1024
#define DI 4096
#define NVOC 32000
#define NROWS 4096
#define KROWS 8192

typedef __nv_bfloat16 bf16;

__device__ __forceinline__ uint32_t smem_u32(const void* p){
    uint32_t a; asm("{ .reg .u64 t; cvta.to.shared.u64 t, %1; cvt.u32.u64 %0, t; }":"=r"(a):"l"(p)); return a;
}
__device__ __forceinline__ void cpa16(uint32_t dst, const void* src){
    asm volatile("cp.async.cg.shared.global [%0], [%1], 16;"::"r"(dst),"l"(src));
}
#define CPA_COMMIT() asm volatile("cp.async.commit_group;":::"memory")
#define CPA_WAIT1()  asm volatile("cp.async.wait_group 1;":::"memory")

__device__ __forceinline__ void ldm_x4(uint32_t& r0,uint32_t& r1,uint32_t& r2,uint32_t& r3,uint32_t a){
    asm volatile("ldmatrix.sync.aligned.m8n8.x4.shared.b16 {%0,%1,%2,%3}, [%4];"
        :"=r"(r0),"=r"(r1),"=r"(r2),"=r"(r3):"r"(a));
}
__device__ __forceinline__ void ldm_x2(uint32_t& r0,uint32_t& r1,uint32_t a){
    asm volatile("ldmatrix.sync.aligned.m8n8.x2.shared.b16 {%0,%1}, [%2];"
        :"=r"(r0),"=r"(r1):"r"(a));
}
__device__ __forceinline__ void ldm_x2t(uint32_t& r0,uint32_t& r1,uint32_t a){
    asm volatile("ldmatrix.sync.aligned.m8n8.x2.trans.shared.b16 {%0,%1}, [%2];"
        :"=r"(r0),"=r"(r1):"r"(a));
}
__device__ __forceinline__ void mma16816(float* c, const uint32_t* a, const uint32_t* b){
    asm volatile("mma.sync.aligned.m16n8k16.row.col.f32.bf16.bf16.f32 "
        "{%0,%1,%2,%3}, {%4,%5,%6,%7}, {%8,%9}, {%0,%1,%2,%3};"
        : "+f"(c[0]),"+f"(c[1]),"+f"(c[2]),"+f"(c[3])
        : "r"(a[0]),"r"(a[1]),"r"(a[2]),"r"(a[3]),"r"(b[0]),"r"(b[1]));
}
__device__ __forceinline__ void split_store2(bf16* h, bf16* l, size_t idx, float a, float b){
    bf16 ha=__float2bfloat16(a), hb=__float2bfloat16(b);
    *(__nv_bfloat162*)(h+idx) = __halves2bfloat162(ha,hb);
    *(__nv_bfloat162*)(l+idx) = __halves2bfloat162(__float2bfloat16(a-__bfloat162float(ha)),
                                                   __float2bfloat16(b-__bfloat162float(hb)));
}

/* -------- static scratch -------- */
__device__ float g_core[NROWS*DM];
__device__ float g_q[NROWS*HD];
__device__ float g_kv[KROWS*2*HD];
__device__ float g_rk[KLEN*HD];
__device__ float g_posb[KLEN*DM];
__device__ float g_score[67108864];        /* AC [128][512][1024] */
__device__ float g_bd[67108864];           /* BDfull              */
__device__ float g_tmp[NROWS*DM];
__device__ float g_ff[NROWS*DI];
__device__ float g_logits[131072000];
__device__ bf16 g_wqT_h[6*DM*HD],    g_wqT_l[6*DM*HD];
__device__ bf16 g_wkvT_h[6*DM*2*HD], g_wkvT_l[6*DM*2*HD];
__device__ bf16 g_wrT_h[6*DM*HD],    g_wrT_l[6*DM*HD];
__device__ bf16 g_woT_h[6*HD*DM],    g_woT_l[6*HD*DM];
__device__ bf16 g_w1T_h[6*DM*DI],    g_w1T_l[6*DM*DI];
__device__ bf16 g_w2T_h[6*DI*DM],    g_w2T_l[6*DI*DM];
__device__ bf16 g_embB_h[NVOC*DM],   g_embB_l[NVOC*DM];
__device__ bf16 g_cA_h[NROWS*DM], g_cA_l[NROWS*DM];
__device__ bf16 g_xA_h[KROWS*DM], g_xA_l[KROWS*DM];
__device__ bf16 g_vA_h[NROWS*HD], g_vA_l[NROWS*HD];
__device__ bf16 g_fA_h[NROWS*DI], g_fA_l[NROWS*DI];
__device__ bf16 g_pA_h[KLEN*DM],  g_pA_l[KLEN*DM];
/* attention bf16 operands */
__device__ bf16 g_QWh[128*512*64], g_QWl[128*512*64];
__device__ bf16 g_QRh[128*512*64], g_QRl[128*512*64];
__device__ bf16 g_Kh[128*1024*64], g_Kl[128*1024*64];
__device__ bf16 g_Vh[128*1024*64], g_Vl[128*1024*64];
__device__ bf16 g_RKh[16*1024*64], g_RKl[16*1024*64];
__device__ bf16 g_Ph[67108864], g_Pl[67108864];

/* -------- converters -------- */
__global__ void conv_hl_kernel(const float* __restrict__ in,
    bf16* __restrict__ h, bf16* __restrict__ l, int n4)
{
    int i = blockIdx.x*blockDim.x + threadIdx.x;
    if(i >= n4) return;
    float4 v = ((const float4*)in)[i];
    split_store2(h, l, (size_t)i*4,   v.x, v.y);
    split_store2(h, l, (size_t)i*4+2, v.z, v.w);
}
__global__ void convT_kernel(const float* __restrict__ in,
    bf16* __restrict__ h, bf16* __restrict__ l, int K, int N)
{
    __shared__ float t[32][33];
    const int n0 = blockIdx.x*32, k0 = blockIdx.y*32;
    const size_t lay = (size_t)blockIdx.z*K*N;
    const int tx = threadIdx.x, ty = threadIdx.y;
#pragma unroll
    for(int e=0;e<4;e++) t[ty+8*e][tx] = in[lay + (size_t)(k0+ty+8*e)*N + n0+tx];
    __syncthreads();
#pragma unroll
    for(int e=0;e<4;e++){
        float x = t[tx][ty+8*e];
        size_t o = lay + (size_t)(n0+ty+8*e)*K + k0+tx;
        bf16 hx = __float2bfloat16(x);
        h[o] = hx; l[o] = __float2bfloat16(x-__bfloat162float(hx));
    }
}

/* -------- repacks -------- */
__global__ void __launch_bounds__(256) repack_q(
    const float* __restrict__ qb, const float* __restrict__ rwb, const float* __restrict__ rrb,
    bf16* __restrict__ QWh, bf16* __restrict__ QWl, bf16* __restrict__ QRh, bf16* __restrict__ QRl)
{
    const int gi = blockIdx.x*256 + threadIdx.x;   /* over 4096*256 */
    const int r = gi >> 8, c4 = (gi & 255) << 2;
    const int i = r >> 3, b = r & 7, n = c4 >> 6, d = c4 & 63;
    float4 q = *(const float4*)(qb + (size_t)r*HD + c4);
    float4 w = *(const float4*)(rwb + n*64 + d);
    float4 rr = *(const float4*)(rrb + n*64 + d);
    size_t o = ((size_t)((b*16+n)*512 + i))*64 + d;
    split_store2(QWh, QWl, o,   q.x+w.x, q.y+w.y);
    split_store2(QWh, QWl, o+2, q.z+w.z, q.w+w.w);
    split_store2(QRh, QRl, o,   q.x+rr.x, q.y+rr.y);
    split_store2(QRh, QRl, o+2, q.z+rr.z, q.w+rr.w);
}
__global__ void __launch_bounds__(256) repack_kv(
    const float* __restrict__ kvb,
    bf16* __restrict__ Kh, bf16* __restrict__ Kl, bf16* __restrict__ Vh, bf16* __restrict__ Vl)
{
    const int gi = blockIdx.x*256 + threadIdx.x;   /* over 8192*512 */
    const int r = gi >> 9, c4 = (gi & 511) << 2;
    const int j = r >> 3, b = r & 7;
    float4 v = *(const float4*)(kvb + (size_t)r*2048 + c4);
    bf16 *H, *L; int cc;
    if(c4 < 1024){ H=Kh; L=Kl; cc=c4; } else { H=Vh; L=Vl; cc=c4-1024; }
    const int n = cc >> 6, d = cc & 63;
    size_t o = ((size_t)((b*16+n)*1024 + j))*64 + d;
    split_store2(H, L, o,   v.x, v.y);
    split_store2(H, L, o+2, v.z, v.w);
}
__global__ void __launch_bounds__(256) repack_rk(
    const float* __restrict__ rkb, bf16* __restrict__ RKh, bf16* __restrict__ RKl)
{
    const int gi = blockIdx.x*256 + threadIdx.x;   /* over 1024*256 */
    const int l = gi >> 8, c4 = (gi & 255) << 2;
    const int n = c4 >> 6, d = c4 & 63;
    float4 v = *(const float4*)(rkb + (size_t)l*HD + c4);
    size_t o = ((size_t)(n*1024 + l))*64 + d;
    split_store2(RKh, RKl, o,   v.x, v.y);
    split_store2(RKh, RKl, o+2, v.z, v.w);
}

/* -------- projection GEMM (unchanged from R6) -------- */
#define MSTRIDE 40
#define MASTG   (128*MSTRIDE)
#define MSTGE   (2*MASTG)
#define MSMEM   (3*MSTGE*2)

template<int EPI>
__global__ void __launch_bounds__(256,2) mgemm(
    const bf16* __restrict__ Ah, const bf16* __restrict__ Al,
    const bf16* __restrict__ Bh, const bf16* __restrict__ Bl,
    const float* __restrict__ bias, float* __restrict__ C, int M, int N, int K)
{
    extern __shared__ bf16 sm[];
    const uint32_t sb = smem_u32(sm);
    const int tid = threadIdx.x, lane = tid & 31, wid = tid >> 5;
    const int warpM = wid >> 2, warpN = wid & 3;
    const int m0 = blockIdx.x*128, n0 = blockIdx.y*128;
    const int NCK = K >> 5, TOT = 3*NCK;

    float acc[4][4][4];
#pragma unroll
    for(int mi=0;mi<4;mi++)
#pragma unroll
        for(int ni=0;ni<4;ni++)
#pragma unroll
            for(int e=0;e<4;e++) acc[mi][ni][e] = 0.f;

    const int lr0 = tid >> 2,       lk0 = tid & 3;
    const int lr1 = (tid+256) >> 2, lk1 = (tid+256) & 3;

    auto load_chunk = [&](int c, int buf){
        int pass = c / NCK, kc = c - pass*NCK, k0 = kc << 5;
        const bf16* A = (pass==2) ? Al : Ah;
        const bf16* B = (pass==1) ? Bl : Bh;
        uint32_t ab = sb + buf*(MSTGE*2);
        uint32_t bb = ab + MASTG*2;
        cpa16(ab + lr0*80 + lk0*16, A + (size_t)(m0+lr0)*K + k0 + lk0*8);
        cpa16(ab + lr1*80 + lk1*16, A + (size_t)(m0+lr1)*K + k0 + lk1*8);
        cpa16(bb + lr0*80 + lk0*16, B + (size_t)(n0+lr0)*K + k0 + lk0*8);
        cpa16(bb + lr1*80 + lk1*16, B + (size_t)(n0+lr1)*K + k0 + lk1*8);
    };

    load_chunk(0,0); CPA_COMMIT();
    load_chunk(1,1); CPA_COMMIT();

    const int arow = warpM*64 + (lane & 15);
    const int ahalf = lane >> 4;
    const int brow = warpN*32 + (lane & 7);
    const int bhalf = (lane >> 3) & 1;

    for(int c = 0; c < TOT; c++){
        CPA_WAIT1();
        __syncthreads();
        if(c+2 < TOT) load_chunk(c+2, (c+2)%3);
        CPA_COMMIT();

        const int buf = c % 3;
        uint32_t ab = sb + buf*(MSTGE*2);
        uint32_t bb = ab + MASTG*2;
#pragma unroll
        for(int ks=0; ks<2; ks++){
            uint32_t af[4][4], bfr[4][2];
#pragma unroll
            for(int mi=0;mi<4;mi++)
                ldm_x4(af[mi][0],af[mi][1],af[mi][2],af[mi][3],
                       ab + (arow + mi*16)*80 + (ks*2 + ahalf)*16);
#pragma unroll
            for(int ni=0;ni<4;ni++)
                ldm_x2(bfr[ni][0],bfr[ni][1],
                       bb + (brow + ni*8)*80 + (ks*2 + bhalf)*16);
#pragma unroll
            for(int mi=0;mi<4;mi++)
#pragma unroll
                for(int ni=0;ni<4;ni++)
                    mma16816(acc[mi][ni], af[mi], bfr[ni]);
        }
    }

#pragma unroll
    for(int mi=0;mi<4;mi++){
        const int row = m0 + warpM*64 + mi*16 + (lane>>2);
#pragma unroll
        for(int ni=0;ni<4;ni++){
            const int col = n0 + warpN*32 + ni*8 + (lane&3)*2;
            float c0=acc[mi][ni][0], c1=acc[mi][ni][1];
            float c2=acc[mi][ni][2], c3=acc[mi][ni][3];
            if(EPI>=1){
                float b0 = bias[col], b1 = bias[col+1];
                c0+=b0; c1+=b1; c2+=b0; c3+=b1;
            }
            if(EPI==2){
                c0=fmaxf(c0,0.f); c1=fmaxf(c1,0.f);
                c2=fmaxf(c2,0.f); c3=fmaxf(c3,0.f);
            }
            *(float2*)(C + (size_t)row*N + col)     = make_float2(c0,c1);
            *(float2*)(C + (size_t)(row+8)*N + col) = make_float2(c2,c3);
        }
    }
}

/* -------- batched attention score GEMM (AC / BD) --------
 * M=512, N=1024, K=64, batch z=bn. MODE 0: AC (B batched by z, causal skip)
 * MODE 1: BD (B batched by z&15, anti-diagonal skip). Split-bf16 x3.
 */
template<int MODE>
__global__ void __launch_bounds__(256,2) bgemm(
    const bf16* __restrict__ Ah, const bf16* __restrict__ Al,
    const bf16* __restrict__ Bh, const bf16* __restrict__ Bl,
    float* __restrict__ C)
{
    const int m0 = blockIdx.x*128, n0 = blockIdx.y*128, z = blockIdx.z;
    if(MODE==0){ if(n0 > m0 + 639) return; }
    else       { if(n0 + 127 < 384 - m0) return; }
    extern __shared__ bf16 sm[];
    const uint32_t sb = smem_u32(sm);
    const int tid = threadIdx.x, lane = tid & 31, wid = tid >> 5;
    const int warpM = wid >> 2, warpN = wid & 3;
    const size_t az = (size_t)z*512*64;
    const size_t bz = (size_t)(MODE==0 ? z : (z & 15))*1024*64;
    const bf16* A0h = Ah + az; const bf16* A0l = Al + az;
    const bf16* B0h = Bh + bz; const bf16* B0l = Bl + bz;

    float acc[4][4][4];
#pragma unroll
    for(int mi=0;mi<4;mi++)
#pragma unroll
        for(int ni=0;ni<4;ni++)
#pragma unroll
            for(int e=0;e<4;e++) acc[mi][ni][e] = 0.f;

    const int lr0 = tid >> 2,       lk0 = tid & 3;
    const int lr1 = (tid+256) >> 2, lk1 = (tid+256) & 3;

    auto load_chunk = [&](int c, int buf){
        int pass = c >> 1, k0 = (c & 1) << 5;
        const bf16* A = (pass==2) ? A0l : A0h;
        const bf16* B = (pass==1) ? B0l : B0h;
        uint32_t ab = sb + buf*(MSTGE*2);
        uint32_t bb = ab + MASTG*2;
        cpa16(ab + lr0*80 + lk0*16, A + (size_t)(m0+lr0)*64 + k0 + lk0*8);
        cpa16(ab + lr1*80 + lk1*16, A + (size_t)(m0+lr1)*64 + k0 + lk1*8);
        cpa16(bb + lr0*80 + lk0*16, B + (size_t)(n0+lr0)*64 + k0 + lk0*8);
        cpa16(bb + lr1*80 + lk1*16, B + (size_t)(n0+lr1)*64 + k0 + lk1*8);
    };

    load_chunk(0,0); CPA_COMMIT();
    load_chunk(1,1); CPA_COMMIT();

    const int arow = warpM*64 + (lane & 15);
    const int ahalf = lane >> 4;
    const int brow = warpN*32 + (lane & 7);
    const int bhalf = (lane >> 3) & 1;

    for(int c = 0; c < 6; c++){
        CPA_WAIT1();
        __syncthreads();
        if(c+2 < 6) load_chunk(c+2, (c+2)%3);
        CPA_COMMIT();
        const int buf = c % 3;
        uint32_t ab = sb + buf*(MSTGE*2);
        uint32_t bb = ab + MASTG*2;
#pragma unroll
        for(int ks=0; ks<2; ks++){
            uint32_t af[4][4], bfr[4][2];
#pragma unroll
            for(int mi=0;mi<4;mi++)
                ldm_x4(af[mi][0],af[mi][1],af[mi][2],af[mi][3],
                       ab + (arow + mi*16)*80 + (ks*2 + ahalf)*16);
#pragma unroll
            for(int ni=0;ni<4;ni++)
                ldm_x2(bfr[ni][0],bfr[ni][1],
                       bb + (brow + ni*8)*80 + (ks*2 + bhalf)*16);
#pragma unroll
            for(int mi=0;mi<4;mi++)
#pragma unroll
                for(int ni=0;ni<4;ni++)
                    mma16816(acc[mi][ni], af[mi], bfr[ni]);
        }
    }

    float* Cz = C + (size_t)z*512*1024;
#pragma unroll
    for(int mi=0;mi<4;mi++){
        const int row = m0 + warpM*64 + mi*16 + (lane>>2);
#pragma unroll
        for(int ni=0;ni<4;ni++){
            const int col = n0 + warpN*32 + ni*8 + (lane&3)*2;
            *(float2*)(Cz + (size_t)row*1024 + col)     = make_float2(acc[mi][ni][0], acc[mi][ni][1]);
            *(float2*)(Cz + (size_t)(row+8)*1024 + col) = make_float2(acc[mi][ni][2], acc[mi][ni][3]);
        }
    }
}

/* -------- softmax with fused rel-shift; writes prob bf16 hi/lo -------- */
__global__ void __launch_bounds__(256) softmax2(
    const float* __restrict__ ac, const float* __restrict__ bd,
    bf16* __restrict__ Ph, bf16* __restrict__ Pl)
{
    const int i = blockIdx.x, z = blockIdx.y, tid = threadIdx.x;
    const float* A = ac + ((size_t)z*512 + i)*1024;
    const float* B = bd + ((size_t)z*512 + i)*1024 + (511 - i);
    bf16* ph = Ph + ((size_t)z*512 + i)*1024;
    bf16* pl = Pl + ((size_t)z*512 + i)*1024;
    const int cnt = i + 513;
    __shared__ float red[256];

    float sv[4];
    float m = -1e30f;
#pragma unroll
    for(int e=0;e<4;e++){
        int j = tid + 256*e;
        sv[e] = (j < cnt) ? (A[j] + B[j]) * 0.125f : -1e30f;
        m = fmaxf(m, sv[e]);
    }
    red[tid] = m; __syncthreads();
    for(int s=128;s>0;s>>=1){ if(tid<s) red[tid]=fmaxf(red[tid],red[tid+s]); __syncthreads(); }
    m = red[0]; __syncthreads();

    float ev[4], sum = 0.f;
#pragma unroll
    for(int e=0;e<4;e++){
        int j = tid + 256*e;
        ev[e] = (j < cnt) ? expf(sv[e] - m) : 0.f;
        sum += ev[e];
    }
    red[tid] = sum; __syncthreads();
    for(int s=128;s>0;s>>=1){ if(tid<s) red[tid]+=red[tid+s]; __syncthreads(); }
    const float inv = 1.f / red[0];

#pragma unroll
    for(int e=0;e<4;e++){
        int j = tid + 256*e;
        float p = ev[e] * inv;
        bf16 h = __float2bfloat16(p);
        ph[j] = h;
        pl[j] = __float2bfloat16(p - __bfloat162float(h));
    }
}

/* -------- PV batched GEMM: vec = P @ V, K truncated to valid region --------
 * M=512, N=64, K<=1024, batch z. 8 warps, warp tile 16x64. Split x3.
 * Epilogue writes bf16 hi/lo directly to vA in [(i*8+b)*1024 + n*64+d].
 */
#define PVA    10240
#define PVSTG  14848
#define PVSMEM (3*PVSTG)

__global__ void __launch_bounds__(256,2) pvgemm(
    const bf16* __restrict__ Ph, const bf16* __restrict__ Pl,
    const bf16* __restrict__ Vh, const bf16* __restrict__ Vl,
    bf16* __restrict__ Oh, bf16* __restrict__ Ol)
{
    const int m0 = blockIdx.x*128, z = blockIdx.y;
    extern __shared__ bf16 sm[];
    const uint32_t sb = smem_u32(sm);
    const int tid = threadIdx.x, lane = tid & 31, wid = tid >> 5;
    const int Keff = min(1024, m0 + 640);
    const int NCK = (Keff + 31) >> 5, TOT = 3*NCK;
    const size_t pz = (size_t)z*512*1024, vz = (size_t)z*1024*64;
    const bf16* P0h = Ph + pz; const bf16* P0l = Pl + pz;
    const bf16* V0h = Vh + vz; const bf16* V0l = Vl + vz;

    float acc[8][4];
#pragma unroll
    for(int ni=0;ni<8;ni++)
#pragma unroll
        for(int e=0;e<4;e++) acc[ni][e] = 0.f;

    const int alr0 = tid >> 2,       alk0 = tid & 3;
    const int alr1 = (tid+256) >> 2, alk1 = (tid+256) & 3;
    const int blr = tid >> 3, blc = tid & 7;

    auto load_chunk = [&](int c, int buf){
        int pass = c / NCK, kc = c - pass*NCK, k0 = kc << 5;
        const bf16* A = (pass==1) ? P0l : P0h;
        const bf16* B = (pass==2) ? V0l : V0h;
        uint32_t ab = sb + buf*PVSTG;
        uint32_t bb = ab + PVA;
        cpa16(ab + alr0*80 + alk0*16, A + (size_t)(m0+alr0)*1024 + k0 + alk0*8);
        cpa16(ab + alr1*80 + alk1*16, A + (size_t)(m0+alr1)*1024 + k0 + alk1*8);
        cpa16(bb + blr*144 + blc*16,  B + (size_t)(k0+blr)*64 + blc*8);
    };

    load_chunk(0,0); CPA_COMMIT();
    load_chunk(1,1); CPA_COMMIT();

    const int arow = wid*16 + (lane & 15);
    const int ahalf = lane >> 4;
    const int bkrow = lane & 15;

    for(int c = 0; c < TOT; c++){
        CPA_WAIT1();
        __syncthreads();
        if(c+2 < TOT) load_chunk(c+2, (c+2)%3);
        CPA_COMMIT();
        const int buf = c % 3;
        uint32_t ab = sb + buf*PVSTG;
        uint32_t bb = ab + PVA;
#pragma unroll
        for(int ks=0; ks<2; ks++){
            uint32_t af[4], bfr[8][2];
            ldm_x4(af[0],af[1],af[2],af[3], ab + arow*80 + (ks*2 + ahalf)*16);
#pragma unroll
            for(int ni=0;ni<8;ni++)
                ldm_x2t(bfr[ni][0],bfr[ni][1], bb + (ks*16 + bkrow)*144 + ni*16);
#pragma unroll
            for(int ni=0;ni<8;ni++)
                mma16816(acc[ni], af, bfr[ni]);
        }
    }

    const int b = z >> 4, hn = z & 15;
    const int r1 = lane >> 2, cb = (lane & 3)*2;
    const int i0r = m0 + wid*16 + r1;
#pragma unroll
    for(int ni=0;ni<8;ni++){
        const int col = hn*64 + ni*8 + cb;
        size_t a0 = ((size_t)(i0r*8 + b))*1024 + col;
        size_t a1 = ((size_t)((i0r+8)*8 + b))*1024 + col;
        split_store2(Oh, Ol, a0, acc[ni][0], acc[ni][1]);
        split_store2(Oh, Ol, a1, acc[ni][2], acc[ni][3]);
    }
}

/* -------- misc -------- */
__global__ void __launch_bounds__(256) add_ln_kernel(
    float* __restrict__ core, const float* __restrict__ delta,
    const float* __restrict__ gamma, const float* __restrict__ beta)
{
    const int row=blockIdx.x, tid=threadIdx.x;
    float* x = core + (size_t)row*DM;
    const float* d = delta + (size_t)row*DM;
    __shared__ float red[256];
    float v[4]; float s=0.f;
#pragma unroll
    for(int e=0;e<4;e++){ int idx=tid+e*256; v[e]=x[idx]+d[idx]; s+=v[e]; }
    red[tid]=s; __syncthreads();
    for(int st=128;st>0;st>>=1){ if(tid<st) red[tid]+=red[tid+st]; __syncthreads(); }
    const float mu=red[0]*(1.f/DM); __syncthreads();
    float sq=0.f;
#pragma unroll
    for(int e=0;e<4;e++){ float t=v[e]-mu; sq+=t*t; }
    red[tid]=sq; __syncthreads();
    for(int st=128;st>0;st>>=1){ if(tid<st) red[tid]+=red[tid+st]; __syncthreads(); }
    const float inv=rsqrtf(red[0]*(1.f/DM)+1e-5f);
#pragma unroll
    for(int e=0;e<4;e++){ int idx=tid+e*256; x[idx]=(v[e]-mu)*inv*gamma[idx]+beta[idx]; }
}
__global__ void copy_kernel(float* __restrict__ dst, const float* __restrict__ src, int n4)
{
    int idx = blockIdx.x*blockDim.x + threadIdx.x;
    if(idx<n4) ((float4*)dst)[idx] = ((const float4*)src)[idx];
}
__global__ void embed_kernel(const int* __restrict__ data, const float* __restrict__ embW,
                             float* __restrict__ core)
{
    const int row = blockIdx.x;
    const int tok = data[row];
    ((float4*)(core+(size_t)row*DM))[threadIdx.x] = ((const float4*)(embW+(size_t)tok*DM))[threadIdx.x];
}
__global__ void pos_kernel(float* __restrict__ pos)
{
    const int l = blockIdx.x;
    const float fl = (float)(KLEN-1-l);
    for(int c=threadIdx.x;c<DM;c+=256){
        int f = (c<512)?c:c-512;
        float inv = expf(-((float)(2*f)/(float)DM)*9.210340371976184f);
        float a = fl*inv;
        pos[(size_t)l*DM+c] = (c<512)?sinf(a):cosf(a);
    }
}
__global__ void __launch_bounds__(256) loss_kernel(
    const float* __restrict__ logits, const int* __restrict__ target, float* __restrict__ out)
{
    const int row=blockIdx.x, tid=threadIdx.x;
    const float* L = logits + (size_t)row*NVOC;
    __shared__ float sm2[256], ss[256];
    float m=-1e30f, s=0.f;
    for(int v=tid;v<NVOC;v+=256){
        float x=L[v];
        if(x>m){ s=s*expf(m-x)+1.f; m=x; } else s+=expf(x-m);
    }
    sm2[tid]=m; ss[tid]=s; __syncthreads();
    for(int st=128;st>0;st>>=1){
        if(tid<st){
            float m2=sm2[tid+st], s2=ss[tid+st];
            if(m2>sm2[tid]){ ss[tid]=ss[tid]*expf(sm2[tid]-m2)+s2; sm2[tid]=m2; }
            else ss[tid]+=s2*expf(m2-sm2[tid]);
        }
        __syncthreads();
    }
    if(tid==0){ out[row] = sm2[0]+logf(ss[0]) - L[target[row]]; }
}

/* -------- host -------- */
extern "C" void kernel_launch(void* const* d_in, const int* in_sizes, int n_in,
                              void* d_out, int out_size)
{
    (void)in_sizes; (void)n_in; (void)out_size;
    const int*   data   = (const int*)  d_in[0];
    const int*   target = (const int*)  d_in[1];
    const float* memory = (const float*)d_in[2];
    const float* embW   = (const float*)d_in[3];
    const float* rwb    = (const float*)d_in[4];
    const float* rrb    = (const float*)d_in[5];
    const float* Wq     = (const float*)d_in[6];
    const float* Wkv    = (const float*)d_in[7];
    const float* Wr     = (const float*)d_in[8];
    const float* Wo     = (const float*)d_in[9];
    const float* W1     = (const float*)d_in[10];
    const float* b1     = (const float*)d_in[11];
    const float* W2     = (const float*)d_in[12];
    const float* b2     = (const float*)d_in[13];
    const float* ln1g   = (const float*)d_in[14];
    const float* ln1b   = (const float*)d_in[15];
    const float* ln2g   = (const float*)d_in[16];
    const float* ln2b   = (const float*)d_in[17];
    float* out = (float*)d_out;

    float *core,*qb,*kvb,*rkb,*posb,*score,*bd,*tmpb,*ffb,*logits;
    cudaGetSymbolAddress((void**)&core,g_core);   cudaGetSymbolAddress((void**)&qb,g_q);
    cudaGetSymbolAddress((void**)&kvb,g_kv);      cudaGetSymbolAddress((void**)&rkb,g_rk);
    cudaGetSymbolAddress((void**)&posb,g_posb);   cudaGetSymbolAddress((void**)&score,g_score);
    cudaGetSymbolAddress((void**)&bd,g_bd);       cudaGetSymbolAddress((void**)&tmpb,g_tmp);
    cudaGetSymbolAddress((void**)&ffb,g_ff);      cudaGetSymbolAddress((void**)&logits,g_logits);

    bf16 *wqTh,*wqTl,*wkvTh,*wkvTl,*wrTh,*wrTl,*woTh,*woTl,*w1Th,*w1Tl,*w2Th,*w2Tl,*embBh,*embBl;
    bf16 *cAh,*cAl,*xAh,*xAl,*vAh,*vAl,*fAh,*fAl,*pAh,*pAl;
    bf16 *QWh,*QWl,*QRh,*QRl,*Kh,*Kl,*Vh,*Vl,*RKh,*RKl,*Phb,*Plb;
    cudaGetSymbolAddress((void**)&wqTh,g_wqT_h);   cudaGetSymbolAddress((void**)&wqTl,g_wqT_l);
    cudaGetSymbolAddress((void**)&wkvTh,g_wkvT_h); cudaGetSymbolAddress((void**)&wkvTl,g_wkvT_l);
    cudaGetSymbolAddress((void**)&wrTh,g_wrT_h);   cudaGetSymbolAddress((void**)&wrTl,g_wrT_l);
    cudaGetSymbolAddress((void**)&woTh,g_woT_h);   cudaGetSymbolAddress((void**)&woTl,g_woT_l);
    cudaGetSymbolAddress((void**)&w1Th,g_w1T_h);   cudaGetSymbolAddress((void**)&w1Tl,g_w1T_l);
    cudaGetSymbolAddress((void**)&w2Th,g_w2T_h);   cudaGetSymbolAddress((void**)&w2Tl,g_w2T_l);
    cudaGetSymbolAddress((void**)&embBh,g_embB_h); cudaGetSymbolAddress((void**)&embBl,g_embB_l);
    cudaGetSymbolAddress((void**)&cAh,g_cA_h); cudaGetSymbolAddress((void**)&cAl,g_cA_l);
    cudaGetSymbolAddress((void**)&xAh,g_xA_h); cudaGetSymbolAddress((void**)&xAl,g_xA_l);
    cudaGetSymbolAddress((void**)&vAh,g_vA_h); cudaGetSymbolAddress((void**)&vAl,g_vA_l);
    cudaGetSymbolAddress((void**)&fAh,g_fA_h); cudaGetSymbolAddress((void**)&fAl,g_fA_l);
    cudaGetSymbolAddress((void**)&pAh,g_pA_h); cudaGetSymbolAddress((void**)&pAl,g_pA_l);
    cudaGetSymbolAddress((void**)&QWh,g_QWh); cudaGetSymbolAddress((void**)&QWl,g_QWl);
    cudaGetSymbolAddress((void**)&QRh,g_QRh); cudaGetSymbolAddress((void**)&QRl,g_QRl);
    cudaGetSymbolAddress((void**)&Kh,g_Kh);   cudaGetSymbolAddress((void**)&Kl,g_Kl);
    cudaGetSymbolAddress((void**)&Vh,g_Vh);   cudaGetSymbolAddress((void**)&Vl,g_Vl);
    cudaGetSymbolAddress((void**)&RKh,g_RKh); cudaGetSymbolAddress((void**)&RKl,g_RKl);
    cudaGetSymbolAddress((void**)&Phb,g_Ph);  cudaGetSymbolAddress((void**)&Plb,g_Pl);

    cudaFuncSetAttribute(mgemm<0>, cudaFuncAttributeMaxDynamicSharedMemorySize, MSMEM);
    cudaFuncSetAttribute(mgemm<1>, cudaFuncAttributeMaxDynamicSharedMemorySize, MSMEM);
    cudaFuncSetAttribute(mgemm<2>, cudaFuncAttributeMaxDynamicSharedMemorySize, MSMEM);
    cudaFuncSetAttribute(bgemm<0>, cudaFuncAttributeMaxDynamicSharedMemorySize, MSMEM);
    cudaFuncSetAttribute(bgemm<1>, cudaFuncAttributeMaxDynamicSharedMemorySize, MSMEM);
    cudaFuncSetAttribute(pvgemm,   cudaFuncAttributeMaxDynamicSharedMemorySize, PVSMEM);

    const dim3 cvt(32,8);
    convT_kernel<<<dim3(HD/32,DM/32,6),cvt>>>(Wq, wqTh, wqTl, DM, HD);
    convT_kernel<<<dim3(2*HD/32,DM/32,6),cvt>>>(Wkv, wkvTh, wkvTl, DM, 2*HD);
    convT_kernel<<<dim3(HD/32,DM/32,6),cvt>>>(Wr, wrTh, wrTl, DM, HD);
    convT_kernel<<<dim3(DM/32,HD/32,6),cvt>>>(Wo, woTh, woTl, HD, DM);
    convT_kernel<<<dim3(DI/32,DM/32,6),cvt>>>(W1, w1Th, w1Tl, DM, DI);
    convT_kernel<<<dim3(DM/32,DI/32,6),cvt>>>(W2, w2Th, w2Tl, DI, DM);
    conv_hl_kernel<<<NVOC*DM/4/256,256>>>(embW, embBh, embBl, NVOC*DM/4);

    embed_kernel<<<NROWS,256>>>(data, embW, core);
    pos_kernel<<<KLEN,256>>>(posb);
    conv_hl_kernel<<<KLEN*DM/4/256,256>>>(posb, pAh, pAl, KLEN*DM/4);

    const int CP4 = NROWS*DM/4;

    for(int l=0;l<6;l++){
        copy_kernel<<<4096,256>>>(out + 4096 + (size_t)l*NROWS*DM, core, CP4);

        conv_hl_kernel<<<CP4/256,256>>>(core, cAh, cAl, CP4);
        conv_hl_kernel<<<CP4/256,256>>>(memory + (size_t)l*MLEN*BSZ*DM, xAh, xAl, CP4);
        conv_hl_kernel<<<CP4/256,256>>>(core, xAh + (size_t)MLEN*BSZ*DM, xAl + (size_t)MLEN*BSZ*DM, CP4);

        mgemm<0><<<dim3(NROWS/128, HD/128),   256, MSMEM>>>(cAh, cAl, wqTh + (size_t)l*DM*HD,    wqTl + (size_t)l*DM*HD,    nullptr, qb,  NROWS, HD,   DM);
        mgemm<0><<<dim3(KROWS/128, 2*HD/128), 256, MSMEM>>>(xAh, xAl, wkvTh + (size_t)l*DM*2*HD, wkvTl + (size_t)l*DM*2*HD, nullptr, kvb, KROWS, 2*HD, DM);
        mgemm<0><<<dim3(KLEN/128, HD/128),    256, MSMEM>>>(pAh, pAl, wrTh + (size_t)l*DM*HD,    wrTl + (size_t)l*DM*HD,    nullptr, rkb, KLEN,  HD,   DM);

        repack_q<<<4096,256>>>(qb, rwb, rrb, QWh, QWl, QRh, QRl);
        repack_kv<<<16384,256>>>(kvb, Kh, Kl, Vh, Vl);
        repack_rk<<<1024,256>>>(rkb, RKh, RKl);

        bgemm<0><<<dim3(4,8,128),256,MSMEM>>>(QWh, QWl, Kh, Kl, score);
        bgemm<1><<<dim3(4,8,128),256,MSMEM>>>(QRh, QRl, RKh, RKl, bd);
        softmax2<<<dim3(512,128),256>>>(score, bd, Phb, Plb);
        pvgemm<<<dim3(4,128),256,PVSMEM>>>(Phb, Plb, Vh, Vl, vAh, vAl);

        mgemm<0><<<dim3(NROWS/128, DM/128), 256, MSMEM>>>(vAh, vAl, woTh + (size_t)l*HD*DM, woTl + (size_t)l*HD*DM, nullptr, tmpb, NROWS, DM, HD);
        add_ln_kernel<<<NROWS,256>>>(core, tmpb, ln1g + l*DM, ln1b + l*DM);

        conv_hl_kernel<<<CP4/256,256>>>(core, cAh, cAl, CP4);
        mgemm<2><<<dim3(NROWS/128, DI/128), 256, MSMEM>>>(cAh, cAl, w1Th + (size_t)l*DM*DI, w1Tl + (size_t)l*DM*DI, b1 + l*DI, ffb, NROWS, DI, DM);
        conv_hl_kernel<<<NROWS*DI/4/256,256>>>(ffb, fAh, fAl, NROWS*DI/4);
        mgemm<1><<<dim3(NROWS/128, DM/128), 256, MSMEM>>>(fAh, fAl, w2Th + (size_t)l*DI*DM, w2Tl + (size_t)l*DI*DM, b2 + l*DM, tmpb, NROWS, DM, DI);
        add_ln_kernel<<<NROWS,256>>>(core, tmpb, ln2g + l*DM, ln2b + l*DM);
    }

    conv_hl_kernel<<<CP4/256,256>>>(core, cAh, cAl, CP4);
    mgemm<0><<<dim3(NROWS/128, NVOC/128), 256, MSMEM>>>(cAh, cAl, embBh, embBl, nullptr, logits, NROWS, NVOC, DM);
    loss_kernel<<<NROWS,256>>>(logits, target, out);
}

// round 11
// speedup vs baseline: 2.4295x; 1.0102x over previous
#include <cuda_runtime.h>
#include <cuda_bf16.h>
#include <math.h>
#include <stdint.h>

#define QLEN 512
#define MLEN 512
#define KLEN 1024
#define BSZ 8
#define DH 64
#define DM 1024
#define HD 1024
#define DI 4096
#define NVOC 32000
#define NROWS 4096
#define KROWS 8192

typedef __nv_bfloat16 bf16;

__device__ __forceinline__ uint32_t smem_u32(const void* p){
    uint32_t a; asm("{ .reg .u64 t; cvta.to.shared.u64 t, %1; cvt.u32.u64 %0, t; }":"=r"(a):"l"(p)); return a;
}
__device__ __forceinline__ void cpa16(uint32_t dst, const void* src){
    asm volatile("cp.async.cg.shared.global [%0], [%1], 16;"::"r"(dst),"l"(src));
}
#define CPA_COMMIT() asm volatile("cp.async.commit_group;":::"memory")
#define CPA_WAIT1()  asm volatile("cp.async.wait_group 1;":::"memory")

__device__ __forceinline__ void ldm_x4(uint32_t& r0,uint32_t& r1,uint32_t& r2,uint32_t& r3,uint32_t a){
    asm volatile("ldmatrix.sync.aligned.m8n8.x4.shared.b16 {%0,%1,%2,%3}, [%4];"
        :"=r"(r0),"=r"(r1),"=r"(r2),"=r"(r3):"r"(a));
}
__device__ __forceinline__ void ldm_x2(uint32_t& r0,uint32_t& r1,uint32_t a){
    asm volatile("ldmatrix.sync.aligned.m8n8.x2.shared.b16 {%0,%1}, [%2];"
        :"=r"(r0),"=r"(r1):"r"(a));
}
__device__ __forceinline__ void ldm_x2t(uint32_t& r0,uint32_t& r1,uint32_t a){
    asm volatile("ldmatrix.sync.aligned.m8n8.x2.trans.shared.b16 {%0,%1}, [%2];"
        :"=r"(r0),"=r"(r1):"r"(a));
}
__device__ __forceinline__ void mma16816(float* c, const uint32_t* a, const uint32_t* b){
    asm volatile("mma.sync.aligned.m16n8k16.row.col.f32.bf16.bf16.f32 "
        "{%0,%1,%2,%3}, {%4,%5,%6,%7}, {%8,%9}, {%0,%1,%2,%3};"
        : "+f"(c[0]),"+f"(c[1]),"+f"(c[2]),"+f"(c[3])
        : "r"(a[0]),"r"(a[1]),"r"(a[2]),"r"(a[3]),"r"(b[0]),"r"(b[1]));
}
__device__ __forceinline__ void split_store2(bf16* h, bf16* l, size_t idx, float a, float b){
    bf16 ha=__float2bfloat16(a), hb=__float2bfloat16(b);
    *(__nv_bfloat162*)(h+idx) = __halves2bfloat162(ha,hb);
    *(__nv_bfloat162*)(l+idx) = __halves2bfloat162(__float2bfloat16(a-__bfloat162float(ha)),
                                                   __float2bfloat16(b-__bfloat162float(hb)));
}

/* -------- static scratch -------- */
__device__ float g_core[NROWS*DM];
__device__ float g_posb[KLEN*DM];
__device__ float g_score[67108864];        /* AC [128][512][1024] */
__device__ float g_bd[67108864];           /* BDfull              */
__device__ float g_tmp[NROWS*DM];
__device__ float g_logits[131072000];
__device__ bf16 g_wqT_h[6*DM*HD],    g_wqT_l[6*DM*HD];
__device__ bf16 g_wkvT_h[6*DM*2*HD], g_wkvT_l[6*DM*2*HD];
__device__ bf16 g_wrT_h[6*DM*HD],    g_wrT_l[6*DM*HD];
__device__ bf16 g_woT_h[6*HD*DM],    g_woT_l[6*HD*DM];
__device__ bf16 g_w1T_h[6*DM*DI],    g_w1T_l[6*DM*DI];
__device__ bf16 g_w2T_h[6*DI*DM],    g_w2T_l[6*DI*DM];
__device__ bf16 g_embB_h[NVOC*DM],   g_embB_l[NVOC*DM];
__device__ bf16 g_cA_h[NROWS*DM], g_cA_l[NROWS*DM];
__device__ bf16 g_xA_h[KROWS*DM], g_xA_l[KROWS*DM];
__device__ bf16 g_vA_h[NROWS*HD], g_vA_l[NROWS*HD];
__device__ bf16 g_fA_h[NROWS*DI], g_fA_l[NROWS*DI];
__device__ bf16 g_pA_h[KLEN*DM],  g_pA_l[KLEN*DM];
/* attention bf16 operands */
__device__ bf16 g_QWh[128*512*64], g_QWl[128*512*64];
__device__ bf16 g_QRh[128*512*64], g_QRl[128*512*64];
__device__ bf16 g_Kh[128*1024*64], g_Kl[128*1024*64];
__device__ bf16 g_Vh[128*1024*64], g_Vl[128*1024*64];
__device__ bf16 g_RKh[16*1024*64], g_RKl[16*1024*64];
__device__ bf16 g_Ph[67108864], g_Pl[67108864];

/* -------- converters -------- */
__global__ void conv_hl_kernel(const float* __restrict__ in,
    bf16* __restrict__ h, bf16* __restrict__ l, int n4)
{
    int i = blockIdx.x*blockDim.x + threadIdx.x;
    if(i >= n4) return;
    float4 v = ((const float4*)in)[i];
    split_store2(h, l, (size_t)i*4,   v.x, v.y);
    split_store2(h, l, (size_t)i*4+2, v.z, v.w);
}
__global__ void convT_kernel(const float* __restrict__ in,
    bf16* __restrict__ h, bf16* __restrict__ l, int K, int N)
{
    __shared__ float t[32][33];
    const int n0 = blockIdx.x*32, k0 = blockIdx.y*32;
    const size_t lay = (size_t)blockIdx.z*K*N;
    const int tx = threadIdx.x, ty = threadIdx.y;
#pragma unroll
    for(int e=0;e<4;e++) t[ty+8*e][tx] = in[lay + (size_t)(k0+ty+8*e)*N + n0+tx];
    __syncthreads();
#pragma unroll
    for(int e=0;e<4;e++){
        float x = t[tx][ty+8*e];
        size_t o = lay + (size_t)(n0+ty+8*e)*K + k0+tx;
        bf16 hx = __float2bfloat16(x);
        h[o] = hx; l[o] = __float2bfloat16(x-__bfloat162float(hx));
    }
}

/* -------- projection GEMM with fused epilogues --------
 * OUT 0: C fp32        1: (p1,p2) hi/lo row-major
 * OUT 2: Wq -> QW(p1,p2), QR(p3,p4), biases vb1=rwb, vb2=rrb
 * OUT 3: Wkv -> K(p1,p2), V(p3,p4)
 * OUT 4: Wr -> RK(p1,p2)
 */
#define MSTRIDE 40
#define MASTG   (128*MSTRIDE)
#define MSTGE   (2*MASTG)
#define MSMEM   (3*MSTGE*2)

template<int EPI,int OUT>
__global__ void __launch_bounds__(256,2) mgemm(
    const bf16* __restrict__ Ah, const bf16* __restrict__ Al,
    const bf16* __restrict__ Bh, const bf16* __restrict__ Bl,
    const float* __restrict__ bias, float* __restrict__ C,
    bf16* __restrict__ p1, bf16* __restrict__ p2,
    bf16* __restrict__ p3, bf16* __restrict__ p4,
    const float* __restrict__ vb1, const float* __restrict__ vb2,
    int M, int N, int K)
{
    extern __shared__ bf16 sm[];
    const uint32_t sb = smem_u32(sm);
    const int tid = threadIdx.x, lane = tid & 31, wid = tid >> 5;
    const int warpM = wid >> 2, warpN = wid & 3;
    const int m0 = blockIdx.x*128, n0 = blockIdx.y*128;
    const int NCK = K >> 5, TOT = 3*NCK;

    float acc[4][4][4];
#pragma unroll
    for(int mi=0;mi<4;mi++)
#pragma unroll
        for(int ni=0;ni<4;ni++)
#pragma unroll
            for(int e=0;e<4;e++) acc[mi][ni][e] = 0.f;

    const int lr0 = tid >> 2,       lk0 = tid & 3;
    const int lr1 = (tid+256) >> 2, lk1 = (tid+256) & 3;

    auto load_chunk = [&](int c, int buf){
        int pass = c / NCK, kc = c - pass*NCK, k0 = kc << 5;
        const bf16* A = (pass==2) ? Al : Ah;
        const bf16* B = (pass==1) ? Bl : Bh;
        uint32_t ab = sb + buf*(MSTGE*2);
        uint32_t bb = ab + MASTG*2;
        cpa16(ab + lr0*80 + lk0*16, A + (size_t)(m0+lr0)*K + k0 + lk0*8);
        cpa16(ab + lr1*80 + lk1*16, A + (size_t)(m0+lr1)*K + k0 + lk1*8);
        cpa16(bb + lr0*80 + lk0*16, B + (size_t)(n0+lr0)*K + k0 + lk0*8);
        cpa16(bb + lr1*80 + lk1*16, B + (size_t)(n0+lr1)*K + k0 + lk1*8);
    };

    load_chunk(0,0); CPA_COMMIT();
    load_chunk(1,1); CPA_COMMIT();

    const int arow = warpM*64 + (lane & 15);
    const int ahalf = lane >> 4;
    const int brow = warpN*32 + (lane & 7);
    const int bhalf = (lane >> 3) & 1;

    for(int c = 0; c < TOT; c++){
        CPA_WAIT1();
        __syncthreads();
        if(c+2 < TOT) load_chunk(c+2, (c+2)%3);
        CPA_COMMIT();

        const int buf = c % 3;
        uint32_t ab = sb + buf*(MSTGE*2);
        uint32_t bb = ab + MASTG*2;
#pragma unroll
        for(int ks=0; ks<2; ks++){
            uint32_t af[4][4], bfr[4][2];
#pragma unroll
            for(int mi=0;mi<4;mi++)
                ldm_x4(af[mi][0],af[mi][1],af[mi][2],af[mi][3],
                       ab + (arow + mi*16)*80 + (ks*2 + ahalf)*16);
#pragma unroll
            for(int ni=0;ni<4;ni++)
                ldm_x2(bfr[ni][0],bfr[ni][1],
                       bb + (brow + ni*8)*80 + (ks*2 + bhalf)*16);
#pragma unroll
            for(int mi=0;mi<4;mi++)
#pragma unroll
                for(int ni=0;ni<4;ni++)
                    mma16816(acc[mi][ni], af[mi], bfr[ni]);
        }
    }

#pragma unroll
    for(int mi=0;mi<4;mi++){
        const int row = m0 + warpM*64 + mi*16 + (lane>>2);
#pragma unroll
        for(int ni=0;ni<4;ni++){
            const int col = n0 + warpN*32 + ni*8 + (lane&3)*2;
            float c0=acc[mi][ni][0], c1=acc[mi][ni][1];
            float c2=acc[mi][ni][2], c3=acc[mi][ni][3];
            if(EPI>=1){
                float b0 = bias[col], b1 = bias[col+1];
                c0+=b0; c1+=b1; c2+=b0; c3+=b1;
            }
            if(EPI==2){
                c0=fmaxf(c0,0.f); c1=fmaxf(c1,0.f);
                c2=fmaxf(c2,0.f); c3=fmaxf(c3,0.f);
            }
            if(OUT==0){
                *(float2*)(C + (size_t)row*N + col)     = make_float2(c0,c1);
                *(float2*)(C + (size_t)(row+8)*N + col) = make_float2(c2,c3);
            } else if(OUT==1){
                split_store2(p1,p2,(size_t)row*N+col,     c0,c1);
                split_store2(p1,p2,(size_t)(row+8)*N+col, c2,c3);
            } else if(OUT==2){
                const int i = row>>3, b = row&7, n = col>>6, d = col&63;
                float w0=vb1[n*64+d], w1=vb1[n*64+d+1];
                float r0=vb2[n*64+d], r1=vb2[n*64+d+1];
                size_t o = ((size_t)((b*16+n)*512 + i))*64 + d;
                split_store2(p1,p2,o,    c0+w0, c1+w1);
                split_store2(p3,p4,o,    c0+r0, c1+r1);
                split_store2(p1,p2,o+64, c2+w0, c3+w1);
                split_store2(p3,p4,o+64, c2+r0, c3+r1);
            } else if(OUT==3){
                const int j = row>>3, b = row&7;
                int cc = col, sel = 0;
                if(cc >= 1024){ cc -= 1024; sel = 1; }
                const int n = cc>>6, d = cc&63;
                bf16* H = sel ? p3 : p1;
                bf16* L = sel ? p4 : p2;
                size_t o = ((size_t)((b*16+n)*1024 + j))*64 + d;
                split_store2(H,L,o,    c0,c1);
                split_store2(H,L,o+64, c2,c3);
            } else { /* OUT==4 */
                const int n = col>>6, d = col&63;
                size_t o = ((size_t)(n*1024 + row))*64 + d;
                split_store2(p1,p2,o,     c0,c1);
                split_store2(p1,p2,o+512, c2,c3);
            }
        }
    }
}

/* -------- batched attention score GEMM (AC / BD) -------- */
template<int MODE>
__global__ void __launch_bounds__(256,2) bgemm(
    const bf16* __restrict__ Ah, const bf16* __restrict__ Al,
    const bf16* __restrict__ Bh, const bf16* __restrict__ Bl,
    float* __restrict__ C)
{
    const int m0 = blockIdx.x*128, n0 = blockIdx.y*128, z = blockIdx.z;
    if(MODE==0){ if(n0 > m0 + 639) return; }
    else       { if(n0 + 127 < 384 - m0) return; }
    extern __shared__ bf16 sm[];
    const uint32_t sb = smem_u32(sm);
    const int tid = threadIdx.x, lane = tid & 31, wid = tid >> 5;
    const int warpM = wid >> 2, warpN = wid & 3;
    const size_t az = (size_t)z*512*64;
    const size_t bz = (size_t)(MODE==0 ? z : (z & 15))*1024*64;
    const bf16* A0h = Ah + az; const bf16* A0l = Al + az;
    const bf16* B0h = Bh + bz; const bf16* B0l = Bl + bz;

    float acc[4][4][4];
#pragma unroll
    for(int mi=0;mi<4;mi++)
#pragma unroll
        for(int ni=0;ni<4;ni++)
#pragma unroll
            for(int e=0;e<4;e++) acc[mi][ni][e] = 0.f;

    const int lr0 = tid >> 2,       lk0 = tid & 3;
    const int lr1 = (tid+256) >> 2, lk1 = (tid+256) & 3;

    auto load_chunk = [&](int c, int buf){
        int pass = c >> 1, k0 = (c & 1) << 5;
        const bf16* A = (pass==2) ? A0l : A0h;
        const bf16* B = (pass==1) ? B0l : B0h;
        uint32_t ab = sb + buf*(MSTGE*2);
        uint32_t bb = ab + MASTG*2;
        cpa16(ab + lr0*80 + lk0*16, A + (size_t)(m0+lr0)*64 + k0 + lk0*8);
        cpa16(ab + lr1*80 + lk1*16, A + (size_t)(m0+lr1)*64 + k0 + lk1*8);
        cpa16(bb + lr0*80 + lk0*16, B + (size_t)(n0+lr0)*64 + k0 + lk0*8);
        cpa16(bb + lr1*80 + lk1*16, B + (size_t)(n0+lr1)*64 + k0 + lk1*8);
    };

    load_chunk(0,0); CPA_COMMIT();
    load_chunk(1,1); CPA_COMMIT();

    const int arow = warpM*64 + (lane & 15);
    const int ahalf = lane >> 4;
    const int brow = warpN*32 + (lane & 7);
    const int bhalf = (lane >> 3) & 1;

    for(int c = 0; c < 6; c++){
        CPA_WAIT1();
        __syncthreads();
        if(c+2 < 6) load_chunk(c+2, (c+2)%3);
        CPA_COMMIT();
        const int buf = c % 3;
        uint32_t ab = sb + buf*(MSTGE*2);
        uint32_t bb = ab + MASTG*2;
#pragma unroll
        for(int ks=0; ks<2; ks++){
            uint32_t af[4][4], bfr[4][2];
#pragma unroll
            for(int mi=0;mi<4;mi++)
                ldm_x4(af[mi][0],af[mi][1],af[mi][2],af[mi][3],
                       ab + (arow + mi*16)*80 + (ks*2 + ahalf)*16);
#pragma unroll
            for(int ni=0;ni<4;ni++)
                ldm_x2(bfr[ni][0],bfr[ni][1],
                       bb + (brow + ni*8)*80 + (ks*2 + bhalf)*16);
#pragma unroll
            for(int mi=0;mi<4;mi++)
#pragma unroll
                for(int ni=0;ni<4;ni++)
                    mma16816(acc[mi][ni], af[mi], bfr[ni]);
        }
    }

    float* Cz = C + (size_t)z*512*1024;
#pragma unroll
    for(int mi=0;mi<4;mi++){
        const int row = m0 + warpM*64 + mi*16 + (lane>>2);
#pragma unroll
        for(int ni=0;ni<4;ni++){
            const int col = n0 + warpN*32 + ni*8 + (lane&3)*2;
            *(float2*)(Cz + (size_t)row*1024 + col)     = make_float2(acc[mi][ni][0], acc[mi][ni][1]);
            *(float2*)(Cz + (size_t)(row+8)*1024 + col) = make_float2(acc[mi][ni][2], acc[mi][ni][3]);
        }
    }
}

/* -------- softmax with fused rel-shift; writes prob bf16 hi/lo -------- */
__global__ void __launch_bounds__(256) softmax2(
    const float* __restrict__ ac, const float* __restrict__ bd,
    bf16* __restrict__ Ph, bf16* __restrict__ Pl)
{
    const int i = blockIdx.x, z = blockIdx.y, tid = threadIdx.x;
    const float* A = ac + ((size_t)z*512 + i)*1024;
    const float* B = bd + ((size_t)z*512 + i)*1024 + (511 - i);
    bf16* ph = Ph + ((size_t)z*512 + i)*1024;
    bf16* pl = Pl + ((size_t)z*512 + i)*1024;
    const int cnt = i + 513;
    __shared__ float red[256];

    float sv[4];
    float m = -1e30f;
#pragma unroll
    for(int e=0;e<4;e++){
        int j = tid + 256*e;
        sv[e] = (j < cnt) ? (A[j] + B[j]) * 0.125f : -1e30f;
        m = fmaxf(m, sv[e]);
    }
    red[tid] = m; __syncthreads();
    for(int s=128;s>0;s>>=1){ if(tid<s) red[tid]=fmaxf(red[tid],red[tid+s]); __syncthreads(); }
    m = red[0]; __syncthreads();

    float ev[4], sum = 0.f;
#pragma unroll
    for(int e=0;e<4;e++){
        int j = tid + 256*e;
        ev[e] = (j < cnt) ? expf(sv[e] - m) : 0.f;
        sum += ev[e];
    }
    red[tid] = sum; __syncthreads();
    for(int s=128;s>0;s>>=1){ if(tid<s) red[tid]+=red[tid+s]; __syncthreads(); }
    const float inv = 1.f / red[0];

#pragma unroll
    for(int e=0;e<4;e++){
        int j = tid + 256*e;
        float p = ev[e] * inv;
        bf16 h = __float2bfloat16(p);
        ph[j] = h;
        pl[j] = __float2bfloat16(p - __bfloat162float(h));
    }
}

/* -------- PV batched GEMM -------- */
#define PVA    10240
#define PVSTG  14848
#define PVSMEM (3*PVSTG)

__global__ void __launch_bounds__(256,2) pvgemm(
    const bf16* __restrict__ Ph, const bf16* __restrict__ Pl,
    const bf16* __restrict__ Vh, const bf16* __restrict__ Vl,
    bf16* __restrict__ Oh, bf16* __restrict__ Ol)
{
    const int m0 = blockIdx.x*128, z = blockIdx.y;
    extern __shared__ bf16 sm[];
    const uint32_t sb = smem_u32(sm);
    const int tid = threadIdx.x, lane = tid & 31, wid = tid >> 5;
    const int Keff = min(1024, m0 + 640);
    const int NCK = (Keff + 31) >> 5, TOT = 3*NCK;
    const size_t pz = (size_t)z*512*1024, vz = (size_t)z*1024*64;
    const bf16* P0h = Ph + pz; const bf16* P0l = Pl + pz;
    const bf16* V0h = Vh + vz; const bf16* V0l = Vl + vz;

    float acc[8][4];
#pragma unroll
    for(int ni=0;ni<8;ni++)
#pragma unroll
        for(int e=0;e<4;e++) acc[ni][e] = 0.f;

    const int alr0 = tid >> 2,       alk0 = tid & 3;
    const int alr1 = (tid+256) >> 2, alk1 = (tid+256) & 3;
    const int blr = tid >> 3, blc = tid & 7;

    auto load_chunk = [&](int c, int buf){
        int pass = c / NCK, kc = c - pass*NCK, k0 = kc << 5;
        const bf16* A = (pass==1) ? P0l : P0h;
        const bf16* B = (pass==2) ? V0l : V0h;
        uint32_t ab = sb + buf*PVSTG;
        uint32_t bb = ab + PVA;
        cpa16(ab + alr0*80 + alk0*16, A + (size_t)(m0+alr0)*1024 + k0 + alk0*8);
        cpa16(ab + alr1*80 + alk1*16, A + (size_t)(m0+alr1)*1024 + k0 + alk1*8);
        cpa16(bb + blr*144 + blc*16,  B + (size_t)(k0+blr)*64 + blc*8);
    };

    load_chunk(0,0); CPA_COMMIT();
    load_chunk(1,1); CPA_COMMIT();

    const int arow = wid*16 + (lane & 15);
    const int ahalf = lane >> 4;
    const int bkrow = lane & 15;

    for(int c = 0; c < TOT; c++){
        CPA_WAIT1();
        __syncthreads();
        if(c+2 < TOT) load_chunk(c+2, (c+2)%3);
        CPA_COMMIT();
        const int buf = c % 3;
        uint32_t ab = sb + buf*PVSTG;
        uint32_t bb = ab + PVA;
#pragma unroll
        for(int ks=0; ks<2; ks++){
            uint32_t af[4], bfr[8][2];
            ldm_x4(af[0],af[1],af[2],af[3], ab + arow*80 + (ks*2 + ahalf)*16);
#pragma unroll
            for(int ni=0;ni<8;ni++)
                ldm_x2t(bfr[ni][0],bfr[ni][1], bb + (ks*16 + bkrow)*144 + ni*16);
#pragma unroll
            for(int ni=0;ni<8;ni++)
                mma16816(acc[ni], af, bfr[ni]);
        }
    }

    const int b = z >> 4, hn = z & 15;
    const int r1 = lane >> 2, cb = (lane & 3)*2;
    const int i0r = m0 + wid*16 + r1;
#pragma unroll
    for(int ni=0;ni<8;ni++){
        const int col = hn*64 + ni*8 + cb;
        size_t a0 = ((size_t)(i0r*8 + b))*1024 + col;
        size_t a1 = ((size_t)((i0r+8)*8 + b))*1024 + col;
        split_store2(Oh, Ol, a0, acc[ni][0], acc[ni][1]);
        split_store2(Oh, Ol, a1, acc[ni][2], acc[ni][3]);
    }
}

/* -------- misc -------- */
__global__ void __launch_bounds__(256) add_ln_kernel(
    float* __restrict__ core, const float* __restrict__ delta,
    const float* __restrict__ gamma, const float* __restrict__ beta,
    bf16* __restrict__ h1, bf16* __restrict__ l1,
    bf16* __restrict__ h2, bf16* __restrict__ l2)
{
    const int row=blockIdx.x, tid=threadIdx.x;
    float* x = core + (size_t)row*DM;
    const float* d = delta + (size_t)row*DM;
    __shared__ float red[256];
    float v[4]; float s=0.f;
#pragma unroll
    for(int e=0;e<4;e++){ int idx=tid+e*256; v[e]=x[idx]+d[idx]; s+=v[e]; }
    red[tid]=s; __syncthreads();
    for(int st=128;st>0;st>>=1){ if(tid<st) red[tid]+=red[tid+st]; __syncthreads(); }
    const float mu=red[0]*(1.f/DM); __syncthreads();
    float sq=0.f;
#pragma unroll
    for(int e=0;e<4;e++){ float t=v[e]-mu; sq+=t*t; }
    red[tid]=sq; __syncthreads();
    for(int st=128;st>0;st>>=1){ if(tid<st) red[tid]+=red[tid+st]; __syncthreads(); }
    const float inv=rsqrtf(red[0]*(1.f/DM)+1e-5f);
#pragma unroll
    for(int e=0;e<2;e++){
        int idx=tid*2 + e*512;     /* pairs for split_store2 */
        float y0=(v[0]-mu)*0.f, y1;
        (void)y0;
        /* recompute pair values: map idx..idx+1 back to v lanes */
        /* v[e'] corresponds to element tid + e'*256; use direct recompute */
        float a0 = x[idx]   + 0.f;  /* placeholder, replaced below */
        (void)a0; (void)y1;
    }
    /* simple per-element store (v[] holds elements tid+e*256) */
#pragma unroll
    for(int e=0;e<4;e++){
        int idx=tid+e*256;
        float y=(v[e]-mu)*inv*gamma[idx]+beta[idx];
        x[idx]=y;
        if(h1){
            bf16 hb=__float2bfloat16(y);
            h1[(size_t)row*DM+idx]=hb;
            l1[(size_t)row*DM+idx]=__float2bfloat16(y-__bfloat162float(hb));
        }
        if(h2){
            bf16 hb=__float2bfloat16(y);
            h2[(size_t)row*DM+idx]=hb;
            l2[(size_t)row*DM+idx]=__float2bfloat16(y-__bfloat162float(hb));
        }
    }
}
__global__ void copy_kernel(float* __restrict__ dst, const float* __restrict__ src, int n4)
{
    int idx = blockIdx.x*blockDim.x + threadIdx.x;
    if(idx<n4) ((float4*)dst)[idx] = ((const float4*)src)[idx];
}
__global__ void embed_kernel(const int* __restrict__ data, const float* __restrict__ embW,
                             float* __restrict__ core,
                             bf16* __restrict__ h1, bf16* __restrict__ l1,
                             bf16* __restrict__ h2, bf16* __restrict__ l2)
{
    const int row = blockIdx.x;
    const int tok = data[row];
    float4 v = ((const float4*)(embW+(size_t)tok*DM))[threadIdx.x];
    ((float4*)(core+(size_t)row*DM))[threadIdx.x] = v;
    size_t o = (size_t)row*DM + threadIdx.x*4;
    split_store2(h1,l1,o,  v.x,v.y); split_store2(h1,l1,o+2, v.z,v.w);
    split_store2(h2,l2,o,  v.x,v.y); split_store2(h2,l2,o+2, v.z,v.w);
}
__global__ void pos_kernel(float* __restrict__ pos)
{
    const int l = blockIdx.x;
    const float fl = (float)(KLEN-1-l);
    for(int c=threadIdx.x;c<DM;c+=256){
        int f = (c<512)?c:c-512;
        float inv = expf(-((float)(2*f)/(float)DM)*9.210340371976184f);
        float a = fl*inv;
        pos[(size_t)l*DM+c] = (c<512)?sinf(a):cosf(a);
    }
}
__global__ void __launch_bounds__(256) loss_kernel(
    const float* __restrict__ logits, const int* __restrict__ target, float* __restrict__ out)
{
    const int row=blockIdx.x, tid=threadIdx.x;
    const float* L = logits + (size_t)row*NVOC;
    __shared__ float sm2[256], ss[256];
    float m=-1e30f, s=0.f;
    for(int v=tid;v<NVOC;v+=256){
        float x=L[v];
        if(x>m){ s=s*expf(m-x)+1.f; m=x; } else s+=expf(x-m);
    }
    sm2[tid]=m; ss[tid]=s; __syncthreads();
    for(int st=128;st>0;st>>=1){
        if(tid<st){
            float m2=sm2[tid+st], s2=ss[tid+st];
            if(m2>sm2[tid]){ ss[tid]=ss[tid]*expf(sm2[tid]-m2)+s2; sm2[tid]=m2; }
            else ss[tid]+=s2*expf(m2-sm2[tid]);
        }
        __syncthreads();
    }
    if(tid==0){ out[row] = sm2[0]+logf(ss[0]) - L[target[row]]; }
}

/* -------- host -------- */
extern "C" void kernel_launch(void* const* d_in, const int* in_sizes, int n_in,
                              void* d_out, int out_size)
{
    (void)in_sizes; (void)n_in; (void)out_size;
    const int*   data   = (const int*)  d_in[0];
    const int*   target = (const int*)  d_in[1];
    const float* memory = (const float*)d_in[2];
    const float* embW   = (const float*)d_in[3];
    const float* rwb    = (const float*)d_in[4];
    const float* rrb    = (const float*)d_in[5];
    const float* Wq     = (const float*)d_in[6];
    const float* Wkv    = (const float*)d_in[7];
    const float* Wr     = (const float*)d_in[8];
    const float* Wo     = (const float*)d_in[9];
    const float* W1     = (const float*)d_in[10];
    const float* b1     = (const float*)d_in[11];
    const float* W2     = (const float*)d_in[12];
    const float* b2     = (const float*)d_in[13];
    const float* ln1g   = (const float*)d_in[14];
    const float* ln1b   = (const float*)d_in[15];
    const float* ln2g   = (const float*)d_in[16];
    const float* ln2b   = (const float*)d_in[17];
    float* out = (float*)d_out;

    float *core,*posb,*score,*bd,*tmpb,*logits;
    cudaGetSymbolAddress((void**)&core,g_core);
    cudaGetSymbolAddress((void**)&posb,g_posb);   cudaGetSymbolAddress((void**)&score,g_score);
    cudaGetSymbolAddress((void**)&bd,g_bd);       cudaGetSymbolAddress((void**)&tmpb,g_tmp);
    cudaGetSymbolAddress((void**)&logits,g_logits);

    bf16 *wqTh,*wqTl,*wkvTh,*wkvTl,*wrTh,*wrTl,*woTh,*woTl,*w1Th,*w1Tl,*w2Th,*w2Tl,*embBh,*embBl;
    bf16 *cAh,*cAl,*xAh,*xAl,*vAh,*vAl,*fAh,*fAl,*pAh,*pAl;
    bf16 *QWh,*QWl,*QRh,*QRl,*Kh,*Kl,*Vh,*Vl,*RKh,*RKl,*Phb,*Plb;
    cudaGetSymbolAddress((void**)&wqTh,g_wqT_h);   cudaGetSymbolAddress((void**)&wqTl,g_wqT_l);
    cudaGetSymbolAddress((void**)&wkvTh,g_wkvT_h); cudaGetSymbolAddress((void**)&wkvTl,g_wkvT_l);
    cudaGetSymbolAddress((void**)&wrTh,g_wrT_h);   cudaGetSymbolAddress((void**)&wrTl,g_wrT_l);
    cudaGetSymbolAddress((void**)&woTh,g_woT_h);   cudaGetSymbolAddress((void**)&woTl,g_woT_l);
    cudaGetSymbolAddress((void**)&w1Th,g_w1T_h);   cudaGetSymbolAddress((void**)&w1Tl,g_w1T_l);
    cudaGetSymbolAddress((void**)&w2Th,g_w2T_h);   cudaGetSymbolAddress((void**)&w2Tl,g_w2T_l);
    cudaGetSymbolAddress((void**)&embBh,g_embB_h); cudaGetSymbolAddress((void**)&embBl,g_embB_l);
    cudaGetSymbolAddress((void**)&cAh,g_cA_h); cudaGetSymbolAddress((void**)&cAl,g_cA_l);
    cudaGetSymbolAddress((void**)&xAh,g_xA_h); cudaGetSymbolAddress((void**)&xAl,g_xA_l);
    cudaGetSymbolAddress((void**)&vAh,g_vA_h); cudaGetSymbolAddress((void**)&vAl,g_vA_l);
    cudaGetSymbolAddress((void**)&fAh,g_fA_h); cudaGetSymbolAddress((void**)&fAl,g_fA_l);
    cudaGetSymbolAddress((void**)&pAh,g_pA_h); cudaGetSymbolAddress((void**)&pAl,g_pA_l);
    cudaGetSymbolAddress((void**)&QWh,g_QWh); cudaGetSymbolAddress((void**)&QWl,g_QWl);
    cudaGetSymbolAddress((void**)&QRh,g_QRh); cudaGetSymbolAddress((void**)&QRl,g_QRl);
    cudaGetSymbolAddress((void**)&Kh,g_Kh);   cudaGetSymbolAddress((void**)&Kl,g_Kl);
    cudaGetSymbolAddress((void**)&Vh,g_Vh);   cudaGetSymbolAddress((void**)&Vl,g_Vl);
    cudaGetSymbolAddress((void**)&RKh,g_RKh); cudaGetSymbolAddress((void**)&RKl,g_RKl);
    cudaGetSymbolAddress((void**)&Phb,g_Ph);  cudaGetSymbolAddress((void**)&Plb,g_Pl);

    cudaFuncSetAttribute(mgemm<0,0>, cudaFuncAttributeMaxDynamicSharedMemorySize, MSMEM);
    cudaFuncSetAttribute(mgemm<1,0>, cudaFuncAttributeMaxDynamicSharedMemorySize, MSMEM);
    cudaFuncSetAttribute(mgemm<2,1>, cudaFuncAttributeMaxDynamicSharedMemorySize, MSMEM);
    cudaFuncSetAttribute(mgemm<0,2>, cudaFuncAttributeMaxDynamicSharedMemorySize, MSMEM);
    cudaFuncSetAttribute(mgemm<0,3>, cudaFuncAttributeMaxDynamicSharedMemorySize, MSMEM);
    cudaFuncSetAttribute(mgemm<0,4>, cudaFuncAttributeMaxDynamicSharedMemorySize, MSMEM);
    cudaFuncSetAttribute(bgemm<0>, cudaFuncAttributeMaxDynamicSharedMemorySize, MSMEM);
    cudaFuncSetAttribute(bgemm<1>, cudaFuncAttributeMaxDynamicSharedMemorySize, MSMEM);
    cudaFuncSetAttribute(pvgemm,   cudaFuncAttributeMaxDynamicSharedMemorySize, PVSMEM);

    const dim3 cvt(32,8);
    convT_kernel<<<dim3(HD/32,DM/32,6),cvt>>>(Wq, wqTh, wqTl, DM, HD);
    convT_kernel<<<dim3(2*HD/32,DM/32,6),cvt>>>(Wkv, wkvTh, wkvTl, DM, 2*HD);
    convT_kernel<<<dim3(HD/32,DM/32,6),cvt>>>(Wr, wrTh, wrTl, DM, HD);
    convT_kernel<<<dim3(DM/32,HD/32,6),cvt>>>(Wo, woTh, woTl, HD, DM);
    convT_kernel<<<dim3(DI/32,DM/32,6),cvt>>>(W1, w1Th, w1Tl, DM, DI);
    convT_kernel<<<dim3(DM/32,DI/32,6),cvt>>>(W2, w2Th, w2Tl, DI, DM);
    conv_hl_kernel<<<NVOC*DM/4/256,256>>>(embW, embBh, embBl, NVOC*DM/4);

    bf16* xA2h = xAh + (size_t)MLEN*BSZ*DM;
    bf16* xA2l = xAl + (size_t)MLEN*BSZ*DM;

    embed_kernel<<<NROWS,256>>>(data, embW, core, cAh, cAl, xA2h, xA2l);
    pos_kernel<<<KLEN,256>>>(posb);
    conv_hl_kernel<<<KLEN*DM/4/256,256>>>(posb, pAh, pAl, KLEN*DM/4);

    const int CP4 = NROWS*DM/4;

    for(int l=0;l<6;l++){
        copy_kernel<<<4096,256>>>(out + 4096 + (size_t)l*NROWS*DM, core, CP4);
        conv_hl_kernel<<<CP4/256,256>>>(memory + (size_t)l*MLEN*BSZ*DM, xAh, xAl, CP4);

        mgemm<0,2><<<dim3(NROWS/128, HD/128),   256, MSMEM>>>(cAh, cAl, wqTh + (size_t)l*DM*HD,    wqTl + (size_t)l*DM*HD,    nullptr, nullptr, QWh, QWl, QRh, QRl, rwb, rrb, NROWS, HD,   DM);
        mgemm<0,3><<<dim3(KROWS/128, 2*HD/128), 256, MSMEM>>>(xAh, xAl, wkvTh + (size_t)l*DM*2*HD, wkvTl + (size_t)l*DM*2*HD, nullptr, nullptr, Kh, Kl, Vh, Vl, nullptr, nullptr, KROWS, 2*HD, DM);
        mgemm<0,4><<<dim3(KLEN/128, HD/128),    256, MSMEM>>>(pAh, pAl, wrTh + (size_t)l*DM*HD,    wrTl + (size_t)l*DM*HD,    nullptr, nullptr, RKh, RKl, nullptr, nullptr, nullptr, nullptr, KLEN,  HD,   DM);

        bgemm<0><<<dim3(4,8,128),256,MSMEM>>>(QWh, QWl, Kh, Kl, score);
        bgemm<1><<<dim3(4,8,128),256,MSMEM>>>(QRh, QRl, RKh, RKl, bd);
        softmax2<<<dim3(512,128),256>>>(score, bd, Phb, Plb);
        pvgemm<<<dim3(4,128),256,PVSMEM>>>(Phb, Plb, Vh, Vl, vAh, vAl);

        mgemm<0,0><<<dim3(NROWS/128, DM/128), 256, MSMEM>>>(vAh, vAl, woTh + (size_t)l*HD*DM, woTl + (size_t)l*HD*DM, nullptr, tmpb, nullptr, nullptr, nullptr, nullptr, nullptr, nullptr, NROWS, DM, HD);
        add_ln_kernel<<<NROWS,256>>>(core, tmpb, ln1g + l*DM, ln1b + l*DM, cAh, cAl, nullptr, nullptr);

        mgemm<2,1><<<dim3(NROWS/128, DI/128), 256, MSMEM>>>(cAh, cAl, w1Th + (size_t)l*DM*DI, w1Tl + (size_t)l*DM*DI, b1 + l*DI, nullptr, fAh, fAl, nullptr, nullptr, nullptr, nullptr, NROWS, DI, DM);
        mgemm<1,0><<<dim3(NROWS/128, DM/128), 256, MSMEM>>>(fAh, fAl, w2Th + (size_t)l*DI*DM, w2Tl + (size_t)l*DI*DM, b2 + l*DM, tmpb, nullptr, nullptr, nullptr, nullptr, nullptr, nullptr, NROWS, DM, DI);
        add_ln_kernel<<<NROWS,256>>>(core, tmpb, ln2g + l*DM, ln2b + l*DM, cAh, cAl, xA2h, xA2l);
    }

    mgemm<0,0><<<dim3(NROWS/128, NVOC/128), 256, MSMEM>>>(cAh, cAl, embBh, embBl, nullptr, logits, nullptr, nullptr, nullptr, nullptr, nullptr, nullptr, NROWS, NVOC, DM);
    loss_kernel<<<NROWS,256>>>(logits, target, out);
}